// round 10
// baseline (speedup 1.0000x reference)
#include <cuda_runtime.h>
#include <math.h>
#include <stdint.h>

#define DIM   1024
#define BT    2
#define NT    2048
#define HEADS 16
#define HD    64
#define MLPD  4096
#define ROWS  (BT*NT)

// ---------------------------------------------------------------------------
// Scratch (static device globals)
// ---------------------------------------------------------------------------
__device__ float g_mod [BT*6*DIM];
__device__ float g_xn  [ROWS*DIM];
__device__ float g_q   [ROWS*DIM];
__device__ float g_k   [ROWS*DIM];
__device__ float g_v   [ROWS*DIM];
__device__ float g_attn[ROWS*DIM];
__device__ float g_h   [(size_t)ROWS*MLPD];
// tf32-rounded AND TRANSPOSED weights: Wq,Wk,Wv,Wo (1M each), W1 (4M), W2 (4M)
__device__ float g_wt  [12*1024*1024];

// ---------------------------------------------------------------------------
// PTX helpers
// ---------------------------------------------------------------------------
__device__ __forceinline__ uint32_t smaddr(const void* p){
    return (uint32_t)__cvta_generic_to_shared(p);
}
__device__ __forceinline__ void cp16(uint32_t d, const void* s){
    asm volatile("cp.async.cg.shared.global [%0], [%1], 16;\n" :: "r"(d), "l"(s));
}
__device__ __forceinline__ void cp_commit(){
    asm volatile("cp.async.commit_group;\n" ::);
}
__device__ __forceinline__ void cp_wait1(){
    asm volatile("cp.async.wait_group 1;\n" ::);
}
__device__ __forceinline__ float to_tf32(float x){
    float r;
    asm volatile("cvt.rna.tf32.f32 %0, %1;\n" : "=f"(r) : "f"(x));
    return r;
}
__device__ __forceinline__ void mma16n8k8(float* c, const float* a, const float* b){
    asm volatile(
        "mma.sync.aligned.m16n8k8.row.col.f32.tf32.tf32.f32 "
        "{%0,%1,%2,%3}, {%4,%5,%6,%7}, {%8,%9}, {%0,%1,%2,%3};\n"
        : "+f"(c[0]), "+f"(c[1]), "+f"(c[2]), "+f"(c[3])
        : "r"(__float_as_uint(a[0])), "r"(__float_as_uint(a[1])),
          "r"(__float_as_uint(a[2])), "r"(__float_as_uint(a[3])),
          "r"(__float_as_uint(b[0])), "r"(__float_as_uint(b[1])));
}

// ---------------------------------------------------------------------------
// 0) Round to tf32 AND transpose: in[K][N] -> out[N][K]
// ---------------------------------------------------------------------------
__global__ void __launch_bounds__(256) round_transpose_kernel(
    const float* __restrict__ in, float* __restrict__ out, int K, int N)
{
    __shared__ float t[32][33];
    int kb = blockIdx.y*32, nb = blockIdx.x*32;
    int tx = threadIdx.x & 31, ty = threadIdx.x >> 5;   // ty 0..7
    #pragma unroll
    for (int j = 0; j < 32; j += 8)
        t[ty+j][tx] = to_tf32(in[(size_t)(kb+ty+j)*N + nb + tx]);
    __syncthreads();
    #pragma unroll
    for (int j = 0; j < 32; j += 8)
        out[(size_t)(nb+ty+j)*K + kb + tx] = t[tx][ty+j];
}

// ---------------------------------------------------------------------------
// 1) mod = silu(t_emb) @ ada_W + ada_b
// ---------------------------------------------------------------------------
__global__ void __launch_bounds__(256) silu_mod_kernel(
    const float* __restrict__ t_emb, const float* __restrict__ adaW,
    const float* __restrict__ adab, float* __restrict__ mod)
{
    __shared__ float st[DIM];
    int b = blockIdx.y;
    int j = blockIdx.x * 256 + threadIdx.x;
    for (int i = threadIdx.x; i < DIM; i += 256) {
        float t = t_emb[b*DIM + i];
        st[i] = t / (1.f + __expf(-t));
    }
    __syncthreads();
    float acc = 0.f;
    #pragma unroll 4
    for (int kk = 0; kk < DIM; kk++)
        acc += st[kk] * adaW[(size_t)kk*6*DIM + j];
    mod[b*6*DIM + j] = acc + adab[j];
}

// ---------------------------------------------------------------------------
// 2) LN + adaLN modulation; output tf32-rounded
// ---------------------------------------------------------------------------
__global__ void __launch_bounds__(256) ln_mod_kernel(
    const float* __restrict__ x, float* __restrict__ out,
    const float* __restrict__ g, const float* __restrict__ bb,
    const float* __restrict__ mod, int shift_chunk, int scale_chunk)
{
    int row = blockIdx.x;
    int b   = row >> 11;
    int tid = threadIdx.x;
    const float* xr = x + (size_t)row*DIM;
    float4 xv = *(const float4*)(xr + tid*4);
    float s  = xv.x + xv.y + xv.z + xv.w;
    float s2 = xv.x*xv.x + xv.y*xv.y + xv.z*xv.z + xv.w*xv.w;
    #pragma unroll
    for (int o = 16; o > 0; o >>= 1) {
        s  += __shfl_xor_sync(0xffffffffu, s,  o);
        s2 += __shfl_xor_sync(0xffffffffu, s2, o);
    }
    __shared__ float ws[8], ws2[8];
    __shared__ float smu, srstd;
    int wid = tid >> 5;
    if ((tid & 31) == 0) { ws[wid] = s; ws2[wid] = s2; }
    __syncthreads();
    if (tid == 0) {
        float S = 0.f, S2 = 0.f;
        #pragma unroll
        for (int i = 0; i < 8; i++) { S += ws[i]; S2 += ws2[i]; }
        float mu  = S  * (1.f/DIM);
        float var = S2 * (1.f/DIM) - mu*mu;
        smu = mu; srstd = rsqrtf(var + 1e-5f);
    }
    __syncthreads();
    float mu = smu, rstd = srstd;
    int c = tid*4;
    const float* mb = mod + b*6*DIM;
    float4 gv = *(const float4*)(g  + c);
    float4 bv = *(const float4*)(bb + c);
    float4 sc = *(const float4*)(mb + scale_chunk*DIM + c);
    float4 sh = *(const float4*)(mb + shift_chunk*DIM + c);
    float4 y;
    y.x = to_tf32(((xv.x-mu)*rstd*gv.x + bv.x)*(1.f+sc.x) + sh.x);
    y.y = to_tf32(((xv.y-mu)*rstd*gv.y + bv.y)*(1.f+sc.y) + sh.y);
    y.z = to_tf32(((xv.z-mu)*rstd*gv.z + bv.z)*(1.f+sc.z) + sh.z);
    y.w = to_tf32(((xv.w-mu)*rstd*gv.w + bv.w)*(1.f+sc.w) + sh.w);
    *(float4*)(out + (size_t)row*DIM + c) = y;
}

// ---------------------------------------------------------------------------
// GEMM: Out(M,Nc) = A(M,K) @ W(K,Nc) with W given TRANSPOSED (Wt[Nc][K]).
//   BM=128, BN=256, BK=32; 256 thr = 8 warps (2M x 4N); warp tile 64x64.
//   sigma4 k-pairing: one float4 per operand row feeds TWO k8 mmas
//   (k-sets {4t,4t+1} and {4t+2,4t+3}); identical on A and B -> exact.
//   Row stride 48 floats -> LDS.128 quad-bank (4*grp+tig)%8, conflict-free.
// ---------------------------------------------------------------------------
#define G_ABUF (128*48)        // 6144 floats
#define G_BBUF (256*48)        // 12288 floats
#define G_BUF  (G_ABUF + G_BBUF)
#define G_SMEM_BYTES (2*G_BUF*4)   // 147456 B

// EPI: 0 = tf32-rounded store, 1 = exact GELU (rounded), 2 = res + gate*acc
template<int EPI>
__global__ void __launch_bounds__(256, 1) gemm_tc(
    const float* __restrict__ A, const float* __restrict__ Wt,
    float* __restrict__ Out, int M, int Nc, int K,
    const float* __restrict__ gate, const float* __restrict__ res)
{
    extern __shared__ float sm[];
    const int tid  = threadIdx.x;
    const int lane = tid & 31, warp = tid >> 5;
    const int grp  = lane >> 2, tig = lane & 3;
    const int wm   = warp & 1,  wn  = warp >> 1;      // 2 x 4
    const int m0   = blockIdx.y * 128, n0 = blockIdx.x * 256;
    const uint32_t smb = smaddr(sm);
    const int nk = K >> 5;

    float acc[4][8][4];
    #pragma unroll
    for (int i = 0; i < 4; i++)
        #pragma unroll
        for (int j = 0; j < 8; j++)
            #pragma unroll
            for (int t = 0; t < 4; t++) acc[i][j][t] = 0.f;

    auto prefetch = [&](int kc, int bufi){
        int off = bufi * G_BUF;
        #pragma unroll
        for (int i = 0; i < 4; i++) {
            int idx = tid + i*256;
            int r = idx >> 3, c4 = (idx & 7) * 4;
            cp16(smb + (uint32_t)(off + r*48 + c4)*4u,
                 A + (size_t)(m0 + r)*K + kc*32 + c4);
        }
        #pragma unroll
        for (int i = 0; i < 8; i++) {
            int idx = tid + i*256;
            int n = idx >> 3, c4 = (idx & 7) * 4;
            cp16(smb + (uint32_t)(off + G_ABUF + n*48 + c4)*4u,
                 Wt + (size_t)(n0 + n)*K + kc*32 + c4);
        }
    };

    prefetch(0, 0); cp_commit();
    int buf = 0;
    for (int kc = 0; kc < nk; kc++) {
        if (kc + 1 < nk) prefetch(kc + 1, buf ^ 1);
        cp_commit();
        cp_wait1();
        __syncthreads();
        const float* As = sm + buf*G_BUF;
        const float* Bs = As + G_ABUF;
        #pragma unroll
        for (int kk = 0; kk < 32; kk += 16) {
            float4 aA[4][2];
            #pragma unroll
            for (int ma = 0; ma < 4; ma++) {
                int r = wm*64 + ma*16 + grp;
                aA[ma][0] = *(const float4*)&As[r    *48 + kk + 4*tig];
                aA[ma][1] = *(const float4*)&As[(r+8)*48 + kk + 4*tig];
            }
            float4 bB[8];
            #pragma unroll
            for (int nb = 0; nb < 8; nb++) {
                int c = wn*64 + nb*8 + grp;
                bB[nb] = *(const float4*)&Bs[c*48 + kk + 4*tig];
            }
            #pragma unroll
            for (int ma = 0; ma < 4; ma++) {
                float a0[4] = {aA[ma][0].x, aA[ma][1].x, aA[ma][0].y, aA[ma][1].y};
                float a1[4] = {aA[ma][0].z, aA[ma][1].z, aA[ma][0].w, aA[ma][1].w};
                #pragma unroll
                for (int nb = 0; nb < 8; nb++) {
                    float b0[2] = {bB[nb].x, bB[nb].y};
                    float b1[2] = {bB[nb].z, bB[nb].w};
                    mma16n8k8(acc[ma][nb], a0, b0);
                    mma16n8k8(acc[ma][nb], a1, b1);
                }
            }
        }
        __syncthreads();
        buf ^= 1;
    }

    #pragma unroll
    for (int ma = 0; ma < 4; ma++) {
        int r0 = m0 + wm*64 + ma*16 + grp;
        #pragma unroll
        for (int nb = 0; nb < 8; nb++) {
            int c = n0 + wn*64 + nb*8 + 2*tig;
            float o0 = acc[ma][nb][0], o1 = acc[ma][nb][1];
            float o2 = acc[ma][nb][2], o3 = acc[ma][nb][3];
            if (EPI == 0) {
                o0 = to_tf32(o0); o1 = to_tf32(o1);
                o2 = to_tf32(o2); o3 = to_tf32(o3);
            } else if (EPI == 1) {
                o0 = to_tf32(0.5f*o0*(1.f + erff(o0*0.70710678f)));
                o1 = to_tf32(0.5f*o1*(1.f + erff(o1*0.70710678f)));
                o2 = to_tf32(0.5f*o2*(1.f + erff(o2*0.70710678f)));
                o3 = to_tf32(0.5f*o3*(1.f + erff(o3*0.70710678f)));
            } else if (EPI == 2) {
                int bi = r0 >> 11;
                float2 g2 = *(const float2*)(gate + bi*6*DIM + c);
                float2 ra = *(const float2*)(res + (size_t)r0    *Nc + c);
                float2 rb = *(const float2*)(res + (size_t)(r0+8)*Nc + c);
                o0 = ra.x + g2.x*o0; o1 = ra.y + g2.y*o1;
                o2 = rb.x + g2.x*o2; o3 = rb.y + g2.y*o3;
            }
            *(float2*)(Out + (size_t)r0    *Nc + c) = make_float2(o0, o1);
            *(float2*)(Out + (size_t)(r0+8)*Nc + c) = make_float2(o2, o3);
        }
    }
}

// Fused QKV: grid.x = 12 (sel = bx>>2 picks matrix, n0 = (bx&3)*256)
__global__ void __launch_bounds__(256, 1) gemm_qkv(
    const float* __restrict__ A,
    const float* __restrict__ Wq, const float* __restrict__ Wk,
    const float* __restrict__ Wv,
    float* __restrict__ oq, float* __restrict__ ok, float* __restrict__ ov)
{
    extern __shared__ float sm[];
    const int tid  = threadIdx.x;
    const int lane = tid & 31, warp = tid >> 5;
    const int grp  = lane >> 2, tig = lane & 3;
    const int wm   = warp & 1,  wn  = warp >> 1;
    const int sel  = blockIdx.x >> 2;
    const int m0   = blockIdx.y * 128, n0 = (blockIdx.x & 3) * 256;
    const float* Wt = (sel == 0) ? Wq : (sel == 1) ? Wk : Wv;
    float* Out      = (sel == 0) ? oq : (sel == 1) ? ok : ov;
    const uint32_t smb = smaddr(sm);

    float acc[4][8][4];
    #pragma unroll
    for (int i = 0; i < 4; i++)
        #pragma unroll
        for (int j = 0; j < 8; j++)
            #pragma unroll
            for (int t = 0; t < 4; t++) acc[i][j][t] = 0.f;

    auto prefetch = [&](int kc, int bufi){
        int off = bufi * G_BUF;
        #pragma unroll
        for (int i = 0; i < 4; i++) {
            int idx = tid + i*256;
            int r = idx >> 3, c4 = (idx & 7) * 4;
            cp16(smb + (uint32_t)(off + r*48 + c4)*4u,
                 A + (size_t)(m0 + r)*DIM + kc*32 + c4);
        }
        #pragma unroll
        for (int i = 0; i < 8; i++) {
            int idx = tid + i*256;
            int n = idx >> 3, c4 = (idx & 7) * 4;
            cp16(smb + (uint32_t)(off + G_ABUF + n*48 + c4)*4u,
                 Wt + (size_t)(n0 + n)*DIM + kc*32 + c4);
        }
    };

    prefetch(0, 0); cp_commit();
    int buf = 0;
    for (int kc = 0; kc < DIM/32; kc++) {
        if (kc + 1 < DIM/32) prefetch(kc + 1, buf ^ 1);
        cp_commit();
        cp_wait1();
        __syncthreads();
        const float* As = sm + buf*G_BUF;
        const float* Bs = As + G_ABUF;
        #pragma unroll
        for (int kk = 0; kk < 32; kk += 16) {
            float4 aA[4][2];
            #pragma unroll
            for (int ma = 0; ma < 4; ma++) {
                int r = wm*64 + ma*16 + grp;
                aA[ma][0] = *(const float4*)&As[r    *48 + kk + 4*tig];
                aA[ma][1] = *(const float4*)&As[(r+8)*48 + kk + 4*tig];
            }
            float4 bB[8];
            #pragma unroll
            for (int nb = 0; nb < 8; nb++) {
                int c = wn*64 + nb*8 + grp;
                bB[nb] = *(const float4*)&Bs[c*48 + kk + 4*tig];
            }
            #pragma unroll
            for (int ma = 0; ma < 4; ma++) {
                float a0[4] = {aA[ma][0].x, aA[ma][1].x, aA[ma][0].y, aA[ma][1].y};
                float a1[4] = {aA[ma][0].z, aA[ma][1].z, aA[ma][0].w, aA[ma][1].w};
                #pragma unroll
                for (int nb = 0; nb < 8; nb++) {
                    float b0[2] = {bB[nb].x, bB[nb].y};
                    float b1[2] = {bB[nb].z, bB[nb].w};
                    mma16n8k8(acc[ma][nb], a0, b0);
                    mma16n8k8(acc[ma][nb], a1, b1);
                }
            }
        }
        __syncthreads();
        buf ^= 1;
    }

    #pragma unroll
    for (int ma = 0; ma < 4; ma++) {
        int r0 = m0 + wm*64 + ma*16 + grp;
        #pragma unroll
        for (int nb = 0; nb < 8; nb++) {
            int c = n0 + wn*64 + nb*8 + 2*tig;
            float o0 = to_tf32(acc[ma][nb][0]);
            float o1 = to_tf32(acc[ma][nb][1]);
            float o2 = to_tf32(acc[ma][nb][2]);
            float o3 = to_tf32(acc[ma][nb][3]);
            *(float2*)(Out + (size_t)r0    *DIM + c) = make_float2(o0, o1);
            *(float2*)(Out + (size_t)(r0+8)*DIM + c) = make_float2(o2, o3);
        }
    }
}

// ---------------------------------------------------------------------------
// 4) RoPE (outputs tf32-rounded)
// ---------------------------------------------------------------------------
__global__ void __launch_bounds__(256) rope_kernel(float* __restrict__ q,
                                                   float* __restrict__ k)
{
    int idx = blockIdx.x*256 + threadIdx.x;
    int n = (idx >> 4) & (NT-1);
    float cs[32], sn[32];
    #pragma unroll
    for (int j = 0; j < 32; j++) {
        float invf = expf((float)j * -0.2878231366f);
        float ang  = (float)n * invf;
        sincosf(ang, &sn[j], &cs[j]);
    }
    float* ptrs[2]; ptrs[0] = q + (size_t)idx*64; ptrs[1] = k + (size_t)idx*64;
    #pragma unroll
    for (int tpi = 0; tpi < 2; tpi++) {
        float* p = ptrs[tpi];
        float buf[64];
        #pragma unroll
        for (int u = 0; u < 16; u++) {
            float4 t = *(const float4*)(p + u*4);
            buf[u*4+0] = t.x; buf[u*4+1] = t.y; buf[u*4+2] = t.z; buf[u*4+3] = t.w;
        }
        #pragma unroll
        for (int t = 0; t < 8; t++) {
            float4 lo, hi;
            lo.x = to_tf32(buf[4*t+0]*cs[4*t+0] - buf[8*t+1]*sn[4*t+0]);
            lo.y = to_tf32(buf[4*t+1]*cs[4*t+1] - buf[8*t+3]*sn[4*t+1]);
            lo.z = to_tf32(buf[4*t+2]*cs[4*t+2] - buf[8*t+5]*sn[4*t+2]);
            lo.w = to_tf32(buf[4*t+3]*cs[4*t+3] - buf[8*t+7]*sn[4*t+3]);
            hi.x = to_tf32(buf[32+4*t+0]*cs[4*t+0] + buf[8*t+0]*sn[4*t+0]);
            hi.y = to_tf32(buf[32+4*t+1]*cs[4*t+1] + buf[8*t+2]*sn[4*t+1]);
            hi.z = to_tf32(buf[32+4*t+2]*cs[4*t+2] + buf[8*t+4]*sn[4*t+2]);
            hi.w = to_tf32(buf[32+4*t+3]*cs[4*t+3] + buf[8*t+6]*sn[4*t+3]);
            *(float4*)(p + 4*t)      = lo;
            *(float4*)(p + 32 + 4*t) = hi;
        }
    }
}

// ---------------------------------------------------------------------------
// 5) Flash attention (unchanged from R8: tf32 mma, sigma2 pairing)
// ---------------------------------------------------------------------------
#define F_QS 0
#define F_KS (64*72)
#define F_PS (2*64*72)
#define F_VS (3*64*72)
#define F_SMEM_BYTES ((3*64*72 + 64*76)*4)

__global__ void __launch_bounds__(128) flash_tc(
    const float* __restrict__ q, const float* __restrict__ k,
    const float* __restrict__ v, float* __restrict__ o)
{
    extern __shared__ float sm[];
    float* Qs = sm + F_QS;
    float* Ks = sm + F_KS;
    float* Ps = sm + F_PS;
    float* Vs = sm + F_VS;

    const int qt = blockIdx.x, bh = blockIdx.y;
    const int b = bh >> 4, h = bh & 15;
    const int tid = threadIdx.x;
    const int lane = tid & 31, warp = tid >> 5;
    const int grp = lane >> 2, tig = lane & 3;
    const int wrow = warp * 16;
    const float* qb = q + (size_t)b*NT*DIM + h*HD;
    const float* kb = k + (size_t)b*NT*DIM + h*HD;
    const float* vb = v + (size_t)b*NT*DIM + h*HD;

    #pragma unroll
    for (int i = 0; i < 8; i++) {
        int idx = tid + i*128;
        int r = idx >> 4, c4 = (idx & 15) * 4;
        float4 t = *(const float4*)(qb + (size_t)(qt*64 + r)*DIM + c4);
        t.x *= 0.125f; t.y *= 0.125f; t.z *= 0.125f; t.w *= 0.125f;
        *(float4*)(Qs + r*72 + c4) = t;
    }

    float O[8][4];
    #pragma unroll
    for (int i = 0; i < 8; i++)
        #pragma unroll
        for (int j = 0; j < 4; j++) O[i][j] = 0.f;
    float m0 = -1e30f, m1 = -1e30f, l0 = 0.f, l1 = 0.f;

    for (int kt = 0; kt < NT/64; kt++) {
        __syncthreads();
        #pragma unroll
        for (int i = 0; i < 8; i++) {
            int idx = tid + i*128;
            int r = idx >> 4, c4 = (idx & 15) * 4;
            float4 kv = *(const float4*)(kb + (size_t)(kt*64 + r)*DIM + c4);
            *(float4*)(Ks + r*72 + c4) = kv;
            float4 vv = *(const float4*)(vb + (size_t)(kt*64 + r)*DIM + c4);
            *(float4*)(Vs + r*76 + c4) = vv;
        }
        __syncthreads();

        float s[8][4];
        #pragma unroll
        for (int i = 0; i < 8; i++)
            #pragma unroll
            for (int j = 0; j < 4; j++) s[i][j] = 0.f;
        #pragma unroll
        for (int kk = 0; kk < 64; kk += 8) {
            float af[4];
            float2 p0 = *(const float2*)&Qs[(wrow+grp  )*72 + kk + 2*tig];
            float2 p1 = *(const float2*)&Qs[(wrow+grp+8)*72 + kk + 2*tig];
            af[0] = p0.x; af[1] = p1.x; af[2] = p0.y; af[3] = p1.y;
            #pragma unroll
            for (int nb = 0; nb < 8; nb++) {
                float bf[2];
                float2 qk = *(const float2*)&Ks[(nb*8+grp)*72 + kk + 2*tig];
                bf[0] = qk.x; bf[1] = qk.y;
                mma16n8k8(s[nb], af, bf);
            }
        }

        float mx0 = -1e30f, mx1 = -1e30f;
        #pragma unroll
        for (int nb = 0; nb < 8; nb++) {
            mx0 = fmaxf(mx0, fmaxf(s[nb][0], s[nb][1]));
            mx1 = fmaxf(mx1, fmaxf(s[nb][2], s[nb][3]));
        }
        mx0 = fmaxf(mx0, __shfl_xor_sync(0xffffffffu, mx0, 1));
        mx0 = fmaxf(mx0, __shfl_xor_sync(0xffffffffu, mx0, 2));
        mx1 = fmaxf(mx1, __shfl_xor_sync(0xffffffffu, mx1, 1));
        mx1 = fmaxf(mx1, __shfl_xor_sync(0xffffffffu, mx1, 2));
        float nm0 = fmaxf(m0, mx0), nm1 = fmaxf(m1, mx1);
        float a0 = __expf(m0 - nm0), a1 = __expf(m1 - nm1);
        float rs0 = 0.f, rs1 = 0.f;
        #pragma unroll
        for (int nb = 0; nb < 8; nb++) {
            float p0 = to_tf32(__expf(s[nb][0] - nm0));
            float p1 = to_tf32(__expf(s[nb][1] - nm0));
            float p2 = to_tf32(__expf(s[nb][2] - nm1));
            float p3 = to_tf32(__expf(s[nb][3] - nm1));
            rs0 += p0 + p1; rs1 += p2 + p3;
            *(float2*)(Ps + (wrow+grp  )*72 + nb*8 + 2*tig) = make_float2(p0, p1);
            *(float2*)(Ps + (wrow+grp+8)*72 + nb*8 + 2*tig) = make_float2(p2, p3);
            O[nb][0] *= a0; O[nb][1] *= a0;
            O[nb][2] *= a1; O[nb][3] *= a1;
        }
        rs0 += __shfl_xor_sync(0xffffffffu, rs0, 1);
        rs0 += __shfl_xor_sync(0xffffffffu, rs0, 2);
        rs1 += __shfl_xor_sync(0xffffffffu, rs1, 1);
        rs1 += __shfl_xor_sync(0xffffffffu, rs1, 2);
        l0 = l0*a0 + rs0; l1 = l1*a1 + rs1;
        m0 = nm0; m1 = nm1;
        __syncwarp();

        #pragma unroll
        for (int kk = 0; kk < 64; kk += 8) {
            float af[4];
            float2 p0 = *(const float2*)&Ps[(wrow+grp  )*72 + kk + 2*tig];
            float2 p1 = *(const float2*)&Ps[(wrow+grp+8)*72 + kk + 2*tig];
            af[0] = p0.x; af[1] = p1.x; af[2] = p0.y; af[3] = p1.y;
            #pragma unroll
            for (int nb = 0; nb < 8; nb++) {
                float bf[2];
                bf[0] = Vs[(kk+2*tig  )*76 + nb*8 + grp];
                bf[1] = Vs[(kk+2*tig+1)*76 + nb*8 + grp];
                mma16n8k8(O[nb], af, bf);
            }
        }
        __syncwarp();
    }

    float i0 = 1.f/l0, i1 = 1.f/l1;
    int row = qt*64 + wrow + grp;
    #pragma unroll
    for (int nb = 0; nb < 8; nb++) {
        float* op = o + (size_t)(b*NT + row)*DIM + h*HD + nb*8 + 2*tig;
        *(float2*)op           = make_float2(to_tf32(O[nb][0]*i0), to_tf32(O[nb][1]*i0));
        *(float2*)(op + 8*DIM) = make_float2(to_tf32(O[nb][2]*i1), to_tf32(O[nb][3]*i1));
    }
}

// ---------------------------------------------------------------------------
// Host launcher
// ---------------------------------------------------------------------------
extern "C" void kernel_launch(void* const* d_in, const int* in_sizes, int n_in,
                              void* d_out, int out_size)
{
    const float* x       = (const float*)d_in[0];
    const float* t_emb   = (const float*)d_in[1];
    const float* norm1_g = (const float*)d_in[2];
    const float* norm1_b = (const float*)d_in[3];
    const float* Wq      = (const float*)d_in[4];
    const float* Wk      = (const float*)d_in[5];
    const float* Wv      = (const float*)d_in[6];
    const float* Wo      = (const float*)d_in[7];
    const float* norm2_g = (const float*)d_in[8];
    const float* norm2_b = (const float*)d_in[9];
    const float* W1      = (const float*)d_in[10];
    const float* W2      = (const float*)d_in[11];
    const float* ada_W   = (const float*)d_in[12];
    const float* ada_b   = (const float*)d_in[13];
    float* out = (float*)d_out;

    float *mod, *xn, *q, *k, *v, *attn, *hbuf, *wt;
    cudaGetSymbolAddress((void**)&mod,  g_mod);
    cudaGetSymbolAddress((void**)&xn,   g_xn);
    cudaGetSymbolAddress((void**)&q,    g_q);
    cudaGetSymbolAddress((void**)&k,    g_k);
    cudaGetSymbolAddress((void**)&v,    g_v);
    cudaGetSymbolAddress((void**)&attn, g_attn);
    cudaGetSymbolAddress((void**)&hbuf, g_h);
    cudaGetSymbolAddress((void**)&wt,   g_wt);

    float* wq = wt;                      // [DIM][DIM]   transposed
    float* wk = wt + 1024*1024;
    float* wv = wt + 2*1024*1024;
    float* wo = wt + 3*1024*1024;
    float* w1 = wt + 4*1024*1024;        // [MLPD][DIM]  transposed
    float* w2 = wt + 8*1024*1024;        // [DIM][MLPD]  transposed

    cudaFuncSetAttribute(gemm_qkv,
        cudaFuncAttributeMaxDynamicSharedMemorySize, G_SMEM_BYTES);
    cudaFuncSetAttribute(gemm_tc<1>,
        cudaFuncAttributeMaxDynamicSharedMemorySize, G_SMEM_BYTES);
    cudaFuncSetAttribute(gemm_tc<2>,
        cudaFuncAttributeMaxDynamicSharedMemorySize, G_SMEM_BYTES);
    cudaFuncSetAttribute(flash_tc,
        cudaFuncAttributeMaxDynamicSharedMemorySize, F_SMEM_BYTES);

    // 0. Round + transpose weights (once per launch)
    round_transpose_kernel<<<dim3(32, 32), 256>>>(Wq, wq, DIM, DIM);
    round_transpose_kernel<<<dim3(32, 32), 256>>>(Wk, wk, DIM, DIM);
    round_transpose_kernel<<<dim3(32, 32), 256>>>(Wv, wv, DIM, DIM);
    round_transpose_kernel<<<dim3(32, 32), 256>>>(Wo, wo, DIM, DIM);
    round_transpose_kernel<<<dim3(128, 32), 256>>>(W1, w1, DIM, MLPD);
    round_transpose_kernel<<<dim3(32, 128), 256>>>(W2, w2, MLPD, DIM);

    // 1. adaLN modulation
    silu_mod_kernel<<<dim3(24, BT), 256>>>(t_emb, ada_W, ada_b, mod);
    // 2. LN1 + modulate (shift=0, scale=1)
    ln_mod_kernel<<<ROWS, 256>>>(x, xn, norm1_g, norm1_b, mod, 0, 1);
    // 3. Fused QKV projections (BN=256 -> 4 n-blocks per matrix)
    gemm_qkv<<<dim3(12, ROWS/128), 256, G_SMEM_BYTES>>>(xn, wq, wk, wv, q, k, v);
    // 4. RoPE
    rope_kernel<<<(BT*NT*HEADS)/256, 256>>>(q, k);
    // 5. attention
    flash_tc<<<dim3(NT/64, BT*HEADS), 128, F_SMEM_BYTES>>>(q, k, v, attn);
    // 6. out proj + gated residual (gate_msa = chunk 2) -> d_out
    gemm_tc<2><<<dim3(4, ROWS/128), 256, G_SMEM_BYTES>>>(
        attn, wo, out, ROWS, DIM, DIM, mod + 2*DIM, x);
    // 7. LN2 + modulate (shift=3, scale=4)
    ln_mod_kernel<<<ROWS, 256>>>(out, xn, norm2_g, norm2_b, mod, 3, 4);
    // 8. MLP up + exact GELU
    gemm_tc<1><<<dim3(16, ROWS/128), 256, G_SMEM_BYTES>>>(
        xn, w1, hbuf, ROWS, MLPD, DIM, nullptr, nullptr);
    // 9. MLP down + gated residual (gate_mlp = chunk 5) -> d_out
    gemm_tc<2><<<dim3(4, ROWS/128), 256, G_SMEM_BYTES>>>(
        hbuf, w2, out, ROWS, DIM, MLPD, mod + 5*DIM, out);
}

// round 11
// speedup vs baseline: 1.0547x; 1.0547x over previous
#include <cuda_runtime.h>
#include <math.h>
#include <stdint.h>

#define DIM   1024
#define BT    2
#define NT    2048
#define HEADS 16
#define HD    64
#define MLPD  4096
#define ROWS  (BT*NT)

// ---------------------------------------------------------------------------
// Scratch (static device globals)
// ---------------------------------------------------------------------------
__device__ float g_mod [BT*6*DIM];
__device__ float g_xn  [ROWS*DIM];
__device__ float g_q   [ROWS*DIM];
__device__ float g_k   [ROWS*DIM];
__device__ float g_v   [ROWS*DIM];
__device__ float g_attn[ROWS*DIM];
__device__ float g_h   [(size_t)ROWS*MLPD];
// tf32-rounded weights, contiguous: Wq,Wk,Wv,Wo (1M floats each), W1(4M), W2(4M)
__device__ float g_wt  [12*1024*1024];

// ---------------------------------------------------------------------------
// PTX helpers
// ---------------------------------------------------------------------------
__device__ __forceinline__ uint32_t smaddr(const void* p){
    return (uint32_t)__cvta_generic_to_shared(p);
}
__device__ __forceinline__ void cp16(uint32_t d, const void* s){
    asm volatile("cp.async.cg.shared.global [%0], [%1], 16;\n" :: "r"(d), "l"(s));
}
__device__ __forceinline__ void cp_commit(){
    asm volatile("cp.async.commit_group;\n" ::);
}
__device__ __forceinline__ void cp_wait1(){
    asm volatile("cp.async.wait_group 1;\n" ::);
}
__device__ __forceinline__ float to_tf32(float x){
    float r;
    asm volatile("cvt.rna.tf32.f32 %0, %1;\n" : "=f"(r) : "f"(x));
    return r;
}
__device__ __forceinline__ void mma16n8k8(float* c, const float* a, const float* b){
    asm volatile(
        "mma.sync.aligned.m16n8k8.row.col.f32.tf32.tf32.f32 "
        "{%0,%1,%2,%3}, {%4,%5,%6,%7}, {%8,%9}, {%0,%1,%2,%3};\n"
        : "+f"(c[0]), "+f"(c[1]), "+f"(c[2]), "+f"(c[3])
        : "r"(__float_as_uint(a[0])), "r"(__float_as_uint(a[1])),
          "r"(__float_as_uint(a[2])), "r"(__float_as_uint(a[3])),
          "r"(__float_as_uint(b[0])), "r"(__float_as_uint(b[1])));
}

// ---------------------------------------------------------------------------
// 0) ONE fused prepass: round all 6 weight matrices to tf32 into g_wt.
//    Layout identical to source (no transpose). 3M float4 total.
// ---------------------------------------------------------------------------
__global__ void __launch_bounds__(256) round_all_kernel(
    const float4* __restrict__ Wq, const float4* __restrict__ Wk,
    const float4* __restrict__ Wv, const float4* __restrict__ Wo,
    const float4* __restrict__ W1, const float4* __restrict__ W2,
    float4* __restrict__ dst)
{
    const int Q4 = 256*1024;              // float4 per 1M-float matrix
    int i = blockIdx.x*256 + threadIdx.x; // 0 .. 3M-1
    const float4* s; int off;
    if (i < 4*Q4) {
        int m = i >> 18; off = i & (Q4-1);
        s = (m == 0) ? Wq : (m == 1) ? Wk : (m == 2) ? Wv : Wo;
    } else if (i < 8*Q4) { s = W1; off = i - 4*Q4; }
    else                 { s = W2; off = i - 8*Q4; }
    float4 t = s[off];
    t.x = to_tf32(t.x); t.y = to_tf32(t.y);
    t.z = to_tf32(t.z); t.w = to_tf32(t.w);
    dst[i] = t;
}

// ---------------------------------------------------------------------------
// 1) mod = silu(t_emb) @ ada_W + ada_b
// ---------------------------------------------------------------------------
__global__ void __launch_bounds__(256) silu_mod_kernel(
    const float* __restrict__ t_emb, const float* __restrict__ adaW,
    const float* __restrict__ adab, float* __restrict__ mod)
{
    __shared__ float st[DIM];
    int b = blockIdx.y;
    int j = blockIdx.x * 256 + threadIdx.x;
    for (int i = threadIdx.x; i < DIM; i += 256) {
        float t = t_emb[b*DIM + i];
        st[i] = t / (1.f + __expf(-t));
    }
    __syncthreads();
    float acc = 0.f;
    #pragma unroll 4
    for (int kk = 0; kk < DIM; kk++)
        acc += st[kk] * adaW[(size_t)kk*6*DIM + j];
    mod[b*6*DIM + j] = acc + adab[j];
}

// ---------------------------------------------------------------------------
// 2) LN + adaLN modulation; output tf32-rounded
// ---------------------------------------------------------------------------
__global__ void __launch_bounds__(256) ln_mod_kernel(
    const float* __restrict__ x, float* __restrict__ out,
    const float* __restrict__ g, const float* __restrict__ bb,
    const float* __restrict__ mod, int shift_chunk, int scale_chunk)
{
    int row = blockIdx.x;
    int b   = row >> 11;
    int tid = threadIdx.x;
    const float* xr = x + (size_t)row*DIM;
    float4 xv = *(const float4*)(xr + tid*4);
    float s  = xv.x + xv.y + xv.z + xv.w;
    float s2 = xv.x*xv.x + xv.y*xv.y + xv.z*xv.z + xv.w*xv.w;
    #pragma unroll
    for (int o = 16; o > 0; o >>= 1) {
        s  += __shfl_xor_sync(0xffffffffu, s,  o);
        s2 += __shfl_xor_sync(0xffffffffu, s2, o);
    }
    __shared__ float ws[8], ws2[8];
    __shared__ float smu, srstd;
    int wid = tid >> 5;
    if ((tid & 31) == 0) { ws[wid] = s; ws2[wid] = s2; }
    __syncthreads();
    if (tid == 0) {
        float S = 0.f, S2 = 0.f;
        #pragma unroll
        for (int i = 0; i < 8; i++) { S += ws[i]; S2 += ws2[i]; }
        float mu  = S  * (1.f/DIM);
        float var = S2 * (1.f/DIM) - mu*mu;
        smu = mu; srstd = rsqrtf(var + 1e-5f);
    }
    __syncthreads();
    float mu = smu, rstd = srstd;
    int c = tid*4;
    const float* mb = mod + b*6*DIM;
    float4 gv = *(const float4*)(g  + c);
    float4 bv = *(const float4*)(bb + c);
    float4 sc = *(const float4*)(mb + scale_chunk*DIM + c);
    float4 sh = *(const float4*)(mb + shift_chunk*DIM + c);
    float4 y;
    y.x = to_tf32(((xv.x-mu)*rstd*gv.x + bv.x)*(1.f+sc.x) + sh.x);
    y.y = to_tf32(((xv.y-mu)*rstd*gv.y + bv.y)*(1.f+sc.y) + sh.y);
    y.z = to_tf32(((xv.z-mu)*rstd*gv.z + bv.z)*(1.f+sc.z) + sh.z);
    y.w = to_tf32(((xv.w-mu)*rstd*gv.w + bv.w)*(1.f+sc.w) + sh.w);
    *(float4*)(out + (size_t)row*DIM + c) = y;
}

// ---------------------------------------------------------------------------
// GEMM (R8-best config): Out(M,Nc) = A(M,K) @ W(K,Nc), row-major.
//   BM=BN=128, BK=32, 8 warps (4M x 2N), warp 32x64, 2 CTAs/SM.
// ---------------------------------------------------------------------------
#define G_ABUF 4608            // 128*36 floats
#define G_BBUF 4352            // 32*136 floats
#define G_BUF  (G_ABUF + G_BBUF)
#define G_SMEM_BYTES (2*G_BUF*4)

// EPI: 1 = exact GELU (rounded store), 2 = res + gate*acc (raw store)
template<int EPI>
__global__ void __launch_bounds__(256, 2) gemm_tc(
    const float* __restrict__ A, const float* __restrict__ W,
    float* __restrict__ Out, int M, int Nc, int K,
    const float* __restrict__ gate, const float* __restrict__ res)
{
    extern __shared__ float sm[];
    const int tid  = threadIdx.x;
    const int lane = tid & 31, warp = tid >> 5;
    const int grp  = lane >> 2, tig = lane & 3;
    const int wm   = warp & 3,  wn  = warp >> 2;
    const int m0   = blockIdx.y * 128, n0 = blockIdx.x * 128;
    const uint32_t smb = smaddr(sm);
    const int nk = K >> 5;

    float acc[2][8][4];
    #pragma unroll
    for (int i = 0; i < 2; i++)
        #pragma unroll
        for (int j = 0; j < 8; j++)
            #pragma unroll
            for (int t = 0; t < 4; t++) acc[i][j][t] = 0.f;

    auto prefetch = [&](int kc, int bufi){
        int off = bufi * G_BUF;
        #pragma unroll
        for (int i = 0; i < 4; i++) {
            int idx = tid + i*256;
            int r = idx >> 3, c4 = (idx & 7) * 4;
            cp16(smb + (uint32_t)(off + r*36 + c4)*4u,
                 A + (size_t)(m0 + r)*K + kc*32 + c4);
        }
        #pragma unroll
        for (int i = 0; i < 4; i++) {
            int idx = tid + i*256;
            int r = idx >> 5, c4 = (idx & 31) * 4;
            cp16(smb + (uint32_t)(off + G_ABUF + r*136 + c4)*4u,
                 W + (size_t)(kc*32 + r)*Nc + n0 + c4);
        }
    };

    prefetch(0, 0); cp_commit();
    int buf = 0;
    for (int kc = 0; kc < nk; kc++) {
        if (kc + 1 < nk) prefetch(kc + 1, buf ^ 1);
        cp_commit();
        cp_wait1();
        __syncthreads();
        const float* As = sm + buf*G_BUF;
        const float* Bs = As + G_ABUF;
        #pragma unroll
        for (int kk = 0; kk < 32; kk += 8) {
            float af[2][4], bf[8][2];
            #pragma unroll
            for (int ma = 0; ma < 2; ma++) {
                int r = wm*32 + ma*16 + grp;
                af[ma][0] = As[r    *36 + kk + tig];
                af[ma][1] = As[(r+8)*36 + kk + tig];
                af[ma][2] = As[r    *36 + kk + tig + 4];
                af[ma][3] = As[(r+8)*36 + kk + tig + 4];
            }
            #pragma unroll
            for (int nb = 0; nb < 8; nb++) {
                int c = wn*64 + nb*8 + grp;
                bf[nb][0] = Bs[(kk+tig  )*136 + c];
                bf[nb][1] = Bs[(kk+tig+4)*136 + c];
            }
            #pragma unroll
            for (int ma = 0; ma < 2; ma++)
                #pragma unroll
                for (int nb = 0; nb < 8; nb++)
                    mma16n8k8(acc[ma][nb], af[ma], bf[nb]);
        }
        __syncthreads();
        buf ^= 1;
    }

    #pragma unroll
    for (int ma = 0; ma < 2; ma++) {
        int r0 = m0 + wm*32 + ma*16 + grp;
        #pragma unroll
        for (int nb = 0; nb < 8; nb++) {
            int c = n0 + wn*64 + nb*8 + 2*tig;
            float o0 = acc[ma][nb][0], o1 = acc[ma][nb][1];
            float o2 = acc[ma][nb][2], o3 = acc[ma][nb][3];
            if (EPI == 1) {
                o0 = to_tf32(0.5f*o0*(1.f + erff(o0*0.70710678f)));
                o1 = to_tf32(0.5f*o1*(1.f + erff(o1*0.70710678f)));
                o2 = to_tf32(0.5f*o2*(1.f + erff(o2*0.70710678f)));
                o3 = to_tf32(0.5f*o3*(1.f + erff(o3*0.70710678f)));
            } else if (EPI == 2) {
                int bi = r0 >> 11;
                float2 g2 = *(const float2*)(gate + bi*6*DIM + c);
                float2 ra = *(const float2*)(res + (size_t)r0    *Nc + c);
                float2 rb = *(const float2*)(res + (size_t)(r0+8)*Nc + c);
                o0 = ra.x + g2.x*o0; o1 = ra.y + g2.y*o1;
                o2 = rb.x + g2.x*o2; o3 = rb.y + g2.y*o3;
            }
            *(float2*)(Out + (size_t)r0    *Nc + c) = make_float2(o0, o1);
            *(float2*)(Out + (size_t)(r0+8)*Nc + c) = make_float2(o2, o3);
        }
    }
}

// Fused QKV: grid.x = 24 (sel = bx>>3), tf32-rounded store
__global__ void __launch_bounds__(256, 2) gemm_qkv(
    const float* __restrict__ A,
    const float* __restrict__ Wq, const float* __restrict__ Wk,
    const float* __restrict__ Wv,
    float* __restrict__ oq, float* __restrict__ ok, float* __restrict__ ov)
{
    extern __shared__ float sm[];
    const int tid  = threadIdx.x;
    const int lane = tid & 31, warp = tid >> 5;
    const int grp  = lane >> 2, tig = lane & 3;
    const int wm   = warp & 3,  wn  = warp >> 2;
    const int sel  = blockIdx.x >> 3;
    const int m0   = blockIdx.y * 128, n0 = (blockIdx.x & 7) * 128;
    const float* W = (sel == 0) ? Wq : (sel == 1) ? Wk : Wv;
    float* Out     = (sel == 0) ? oq : (sel == 1) ? ok : ov;
    const uint32_t smb = smaddr(sm);

    float acc[2][8][4];
    #pragma unroll
    for (int i = 0; i < 2; i++)
        #pragma unroll
        for (int j = 0; j < 8; j++)
            #pragma unroll
            for (int t = 0; t < 4; t++) acc[i][j][t] = 0.f;

    auto prefetch = [&](int kc, int bufi){
        int off = bufi * G_BUF;
        #pragma unroll
        for (int i = 0; i < 4; i++) {
            int idx = tid + i*256;
            int r = idx >> 3, c4 = (idx & 7) * 4;
            cp16(smb + (uint32_t)(off + r*36 + c4)*4u,
                 A + (size_t)(m0 + r)*DIM + kc*32 + c4);
        }
        #pragma unroll
        for (int i = 0; i < 4; i++) {
            int idx = tid + i*256;
            int r = idx >> 5, c4 = (idx & 31) * 4;
            cp16(smb + (uint32_t)(off + G_ABUF + r*136 + c4)*4u,
                 W + (size_t)(kc*32 + r)*DIM + n0 + c4);
        }
    };

    prefetch(0, 0); cp_commit();
    int buf = 0;
    for (int kc = 0; kc < DIM/32; kc++) {
        if (kc + 1 < DIM/32) prefetch(kc + 1, buf ^ 1);
        cp_commit();
        cp_wait1();
        __syncthreads();
        const float* As = sm + buf*G_BUF;
        const float* Bs = As + G_ABUF;
        #pragma unroll
        for (int kk = 0; kk < 32; kk += 8) {
            float af[2][4], bf[8][2];
            #pragma unroll
            for (int ma = 0; ma < 2; ma++) {
                int r = wm*32 + ma*16 + grp;
                af[ma][0] = As[r    *36 + kk + tig];
                af[ma][1] = As[(r+8)*36 + kk + tig];
                af[ma][2] = As[r    *36 + kk + tig + 4];
                af[ma][3] = As[(r+8)*36 + kk + tig + 4];
            }
            #pragma unroll
            for (int nb = 0; nb < 8; nb++) {
                int c = wn*64 + nb*8 + grp;
                bf[nb][0] = Bs[(kk+tig  )*136 + c];
                bf[nb][1] = Bs[(kk+tig+4)*136 + c];
            }
            #pragma unroll
            for (int ma = 0; ma < 2; ma++)
                #pragma unroll
                for (int nb = 0; nb < 8; nb++)
                    mma16n8k8(acc[ma][nb], af[ma], bf[nb]);
        }
        __syncthreads();
        buf ^= 1;
    }

    #pragma unroll
    for (int ma = 0; ma < 2; ma++) {
        int r0 = m0 + wm*32 + ma*16 + grp;
        #pragma unroll
        for (int nb = 0; nb < 8; nb++) {
            int c = n0 + wn*64 + nb*8 + 2*tig;
            float o0 = to_tf32(acc[ma][nb][0]);
            float o1 = to_tf32(acc[ma][nb][1]);
            float o2 = to_tf32(acc[ma][nb][2]);
            float o3 = to_tf32(acc[ma][nb][3]);
            *(float2*)(Out + (size_t)r0    *DIM + c) = make_float2(o0, o1);
            *(float2*)(Out + (size_t)(r0+8)*DIM + c) = make_float2(o2, o3);
        }
    }
}

// ---------------------------------------------------------------------------
// 4) RoPE (outputs tf32-rounded)
// ---------------------------------------------------------------------------
__global__ void __launch_bounds__(256) rope_kernel(float* __restrict__ q,
                                                   float* __restrict__ k)
{
    int idx = blockIdx.x*256 + threadIdx.x;
    int n = (idx >> 4) & (NT-1);
    float cs[32], sn[32];
    #pragma unroll
    for (int j = 0; j < 32; j++) {
        float invf = expf((float)j * -0.2878231366f);
        float ang  = (float)n * invf;
        sincosf(ang, &sn[j], &cs[j]);
    }
    float* ptrs[2]; ptrs[0] = q + (size_t)idx*64; ptrs[1] = k + (size_t)idx*64;
    #pragma unroll
    for (int tpi = 0; tpi < 2; tpi++) {
        float* p = ptrs[tpi];
        float buf[64];
        #pragma unroll
        for (int u = 0; u < 16; u++) {
            float4 t = *(const float4*)(p + u*4);
            buf[u*4+0] = t.x; buf[u*4+1] = t.y; buf[u*4+2] = t.z; buf[u*4+3] = t.w;
        }
        #pragma unroll
        for (int t = 0; t < 8; t++) {
            float4 lo, hi;
            lo.x = to_tf32(buf[4*t+0]*cs[4*t+0] - buf[8*t+1]*sn[4*t+0]);
            lo.y = to_tf32(buf[4*t+1]*cs[4*t+1] - buf[8*t+3]*sn[4*t+1]);
            lo.z = to_tf32(buf[4*t+2]*cs[4*t+2] - buf[8*t+5]*sn[4*t+2]);
            lo.w = to_tf32(buf[4*t+3]*cs[4*t+3] - buf[8*t+7]*sn[4*t+3]);
            hi.x = to_tf32(buf[32+4*t+0]*cs[4*t+0] + buf[8*t+0]*sn[4*t+0]);
            hi.y = to_tf32(buf[32+4*t+1]*cs[4*t+1] + buf[8*t+2]*sn[4*t+1]);
            hi.z = to_tf32(buf[32+4*t+2]*cs[4*t+2] + buf[8*t+4]*sn[4*t+2]);
            hi.w = to_tf32(buf[32+4*t+3]*cs[4*t+3] + buf[8*t+6]*sn[4*t+3]);
            *(float4*)(p + 4*t)      = lo;
            *(float4*)(p + 32 + 4*t) = hi;
        }
    }
}

// ---------------------------------------------------------------------------
// 5) Flash attention v2: Q tile 128 rows, 256 threads (8 warps x 16 rows).
//    Each 64-row K/V tile serves 128 Q rows (half the K/V traffic of v1).
//    Smem: Qs[128][72] Ks[64][72] Ps[128][72] Vs[64][76] = ~112 KB, 2 CTA/SM.
// ---------------------------------------------------------------------------
#define F_QS 0
#define F_KS (128*72)
#define F_PS (128*72 + 64*72)
#define F_VS (2*128*72 + 64*72)
#define F_SMEM_BYTES ((2*128*72 + 64*72 + 64*76)*4)

__global__ void __launch_bounds__(256) flash_tc(
    const float* __restrict__ q, const float* __restrict__ k,
    const float* __restrict__ v, float* __restrict__ o)
{
    extern __shared__ float sm[];
    float* Qs = sm + F_QS;
    float* Ks = sm + F_KS;
    float* Ps = sm + F_PS;
    float* Vs = sm + F_VS;

    const int qt = blockIdx.x, bh = blockIdx.y;
    const int b = bh >> 4, h = bh & 15;
    const int tid = threadIdx.x;
    const int lane = tid & 31, warp = tid >> 5;
    const int grp = lane >> 2, tig = lane & 3;
    const int wrow = warp * 16;
    const float* qb = q + (size_t)b*NT*DIM + h*HD;
    const float* kb = k + (size_t)b*NT*DIM + h*HD;
    const float* vb = v + (size_t)b*NT*DIM + h*HD;

    // Q tile: 128 rows (pre-rounded; *0.125f exact)
    #pragma unroll
    for (int i = 0; i < 8; i++) {
        int idx = tid + i*256;
        int r = idx >> 4, c4 = (idx & 15) * 4;
        float4 t = *(const float4*)(qb + (size_t)(qt*128 + r)*DIM + c4);
        t.x *= 0.125f; t.y *= 0.125f; t.z *= 0.125f; t.w *= 0.125f;
        *(float4*)(Qs + r*72 + c4) = t;
    }

    float O[8][4];
    #pragma unroll
    for (int i = 0; i < 8; i++)
        #pragma unroll
        for (int j = 0; j < 4; j++) O[i][j] = 0.f;
    float m0 = -1e30f, m1 = -1e30f, l0 = 0.f, l1 = 0.f;

    for (int kt = 0; kt < NT/64; kt++) {
        __syncthreads();           // prev-iter reads of Ks/Vs complete
        #pragma unroll
        for (int i = 0; i < 4; i++) {
            int idx = tid + i*256;
            int r = idx >> 4, c4 = (idx & 15) * 4;
            float4 kv = *(const float4*)(kb + (size_t)(kt*64 + r)*DIM + c4);
            *(float4*)(Ks + r*72 + c4) = kv;
            float4 vv = *(const float4*)(vb + (size_t)(kt*64 + r)*DIM + c4);
            *(float4*)(Vs + r*76 + c4) = vv;
        }
        __syncthreads();

        // S = Q @ K^T  (16x64 per warp)
        float s[8][4];
        #pragma unroll
        for (int i = 0; i < 8; i++)
            #pragma unroll
            for (int j = 0; j < 4; j++) s[i][j] = 0.f;
        #pragma unroll
        for (int kk = 0; kk < 64; kk += 8) {
            float af[4];
            float2 p0 = *(const float2*)&Qs[(wrow+grp  )*72 + kk + 2*tig];
            float2 p1 = *(const float2*)&Qs[(wrow+grp+8)*72 + kk + 2*tig];
            af[0] = p0.x; af[1] = p1.x; af[2] = p0.y; af[3] = p1.y;
            #pragma unroll
            for (int nb = 0; nb < 8; nb++) {
                float bf[2];
                float2 qk = *(const float2*)&Ks[(nb*8+grp)*72 + kk + 2*tig];
                bf[0] = qk.x; bf[1] = qk.y;
                mma16n8k8(s[nb], af, bf);
            }
        }

        // online softmax for this warp's rows (grp, grp+8)
        float mx0 = -1e30f, mx1 = -1e30f;
        #pragma unroll
        for (int nb = 0; nb < 8; nb++) {
            mx0 = fmaxf(mx0, fmaxf(s[nb][0], s[nb][1]));
            mx1 = fmaxf(mx1, fmaxf(s[nb][2], s[nb][3]));
        }
        mx0 = fmaxf(mx0, __shfl_xor_sync(0xffffffffu, mx0, 1));
        mx0 = fmaxf(mx0, __shfl_xor_sync(0xffffffffu, mx0, 2));
        mx1 = fmaxf(mx1, __shfl_xor_sync(0xffffffffu, mx1, 1));
        mx1 = fmaxf(mx1, __shfl_xor_sync(0xffffffffu, mx1, 2));
        float nm0 = fmaxf(m0, mx0), nm1 = fmaxf(m1, mx1);
        float a0 = __expf(m0 - nm0), a1 = __expf(m1 - nm1);
        float rs0 = 0.f, rs1 = 0.f;
        #pragma unroll
        for (int nb = 0; nb < 8; nb++) {
            float p0 = to_tf32(__expf(s[nb][0] - nm0));
            float p1 = to_tf32(__expf(s[nb][1] - nm0));
            float p2 = to_tf32(__expf(s[nb][2] - nm1));
            float p3 = to_tf32(__expf(s[nb][3] - nm1));
            rs0 += p0 + p1; rs1 += p2 + p3;
            *(float2*)(Ps + (wrow+grp  )*72 + nb*8 + 2*tig) = make_float2(p0, p1);
            *(float2*)(Ps + (wrow+grp+8)*72 + nb*8 + 2*tig) = make_float2(p2, p3);
            O[nb][0] *= a0; O[nb][1] *= a0;
            O[nb][2] *= a1; O[nb][3] *= a1;
        }
        rs0 += __shfl_xor_sync(0xffffffffu, rs0, 1);
        rs0 += __shfl_xor_sync(0xffffffffu, rs0, 2);
        rs1 += __shfl_xor_sync(0xffffffffu, rs1, 1);
        rs1 += __shfl_xor_sync(0xffffffffu, rs1, 2);
        l0 = l0*a0 + rs0; l1 = l1*a1 + rs1;
        m0 = nm0; m1 = nm1;
        __syncwarp();   // P rows are warp-private

        // O += P @ V
        #pragma unroll
        for (int kk = 0; kk < 64; kk += 8) {
            float af[4];
            float2 p0 = *(const float2*)&Ps[(wrow+grp  )*72 + kk + 2*tig];
            float2 p1 = *(const float2*)&Ps[(wrow+grp+8)*72 + kk + 2*tig];
            af[0] = p0.x; af[1] = p1.x; af[2] = p0.y; af[3] = p1.y;
            #pragma unroll
            for (int nb = 0; nb < 8; nb++) {
                float bf[2];
                bf[0] = Vs[(kk+2*tig  )*76 + nb*8 + grp];
                bf[1] = Vs[(kk+2*tig+1)*76 + nb*8 + grp];
                mma16n8k8(O[nb], af, bf);
            }
        }
        __syncwarp();
    }

    float i0 = 1.f/l0, i1 = 1.f/l1;
    int row = qt*128 + wrow + grp;
    #pragma unroll
    for (int nb = 0; nb < 8; nb++) {
        float* op = o + (size_t)(b*NT + row)*DIM + h*HD + nb*8 + 2*tig;
        *(float2*)op           = make_float2(to_tf32(O[nb][0]*i0), to_tf32(O[nb][1]*i0));
        *(float2*)(op + 8*DIM) = make_float2(to_tf32(O[nb][2]*i1), to_tf32(O[nb][3]*i1));
    }
}

// ---------------------------------------------------------------------------
// Host launcher.  Launch order puts flash at index 5 (= ncu -s 5 capture).
// ---------------------------------------------------------------------------
extern "C" void kernel_launch(void* const* d_in, const int* in_sizes, int n_in,
                              void* d_out, int out_size)
{
    const float* x       = (const float*)d_in[0];
    const float* t_emb   = (const float*)d_in[1];
    const float* norm1_g = (const float*)d_in[2];
    const float* norm1_b = (const float*)d_in[3];
    const float* Wq      = (const float*)d_in[4];
    const float* Wk      = (const float*)d_in[5];
    const float* Wv      = (const float*)d_in[6];
    const float* Wo      = (const float*)d_in[7];
    const float* norm2_g = (const float*)d_in[8];
    const float* norm2_b = (const float*)d_in[9];
    const float* W1      = (const float*)d_in[10];
    const float* W2      = (const float*)d_in[11];
    const float* ada_W   = (const float*)d_in[12];
    const float* ada_b   = (const float*)d_in[13];
    float* out = (float*)d_out;

    float *mod, *xn, *q, *k, *v, *attn, *hbuf, *wt;
    cudaGetSymbolAddress((void**)&mod,  g_mod);
    cudaGetSymbolAddress((void**)&xn,   g_xn);
    cudaGetSymbolAddress((void**)&q,    g_q);
    cudaGetSymbolAddress((void**)&k,    g_k);
    cudaGetSymbolAddress((void**)&v,    g_v);
    cudaGetSymbolAddress((void**)&attn, g_attn);
    cudaGetSymbolAddress((void**)&hbuf, g_h);
    cudaGetSymbolAddress((void**)&wt,   g_wt);

    float* wq = wt;
    float* wk = wt + 1024*1024;
    float* wv = wt + 2*1024*1024;
    float* wo = wt + 3*1024*1024;
    float* w1 = wt + 4*1024*1024;
    float* w2 = wt + 8*1024*1024;

    cudaFuncSetAttribute(gemm_qkv,
        cudaFuncAttributeMaxDynamicSharedMemorySize, G_SMEM_BYTES);
    cudaFuncSetAttribute(gemm_tc<1>,
        cudaFuncAttributeMaxDynamicSharedMemorySize, G_SMEM_BYTES);
    cudaFuncSetAttribute(gemm_tc<2>,
        cudaFuncAttributeMaxDynamicSharedMemorySize, G_SMEM_BYTES);
    cudaFuncSetAttribute(flash_tc,
        cudaFuncAttributeMaxDynamicSharedMemorySize, F_SMEM_BYTES);

    // launch 0: fused prepass (round all weights to tf32)
    round_all_kernel<<<12288, 256>>>((const float4*)Wq, (const float4*)Wk,
                                     (const float4*)Wv, (const float4*)Wo,
                                     (const float4*)W1, (const float4*)W2,
                                     (float4*)wt);
    // launch 1: adaLN modulation
    silu_mod_kernel<<<dim3(24, BT), 256>>>(t_emb, ada_W, ada_b, mod);
    // launch 2: LN1 + modulate (shift=0, scale=1)
    ln_mod_kernel<<<ROWS, 256>>>(x, xn, norm1_g, norm1_b, mod, 0, 1);
    // launch 3: fused QKV projections
    gemm_qkv<<<dim3(24, ROWS/128), 256, G_SMEM_BYTES>>>(xn, wq, wk, wv, q, k, v);
    // launch 4: RoPE
    rope_kernel<<<(BT*NT*HEADS)/256, 256>>>(q, k);
    // launch 5: attention (captured by ncu -s 5 -c 1)
    flash_tc<<<dim3(NT/128, BT*HEADS), 256, F_SMEM_BYTES>>>(q, k, v, attn);
    // launch 6: out proj + gated residual (gate_msa = chunk 2) -> d_out
    gemm_tc<2><<<dim3(8, ROWS/128), 256, G_SMEM_BYTES>>>(
        attn, wo, out, ROWS, DIM, DIM, mod + 2*DIM, x);
    // launch 7: LN2 + modulate (shift=3, scale=4)
    ln_mod_kernel<<<ROWS, 256>>>(out, xn, norm2_g, norm2_b, mod, 3, 4);
    // launch 8: MLP up + exact GELU
    gemm_tc<1><<<dim3(32, ROWS/128), 256, G_SMEM_BYTES>>>(
        xn, w1, hbuf, ROWS, MLPD, DIM, nullptr, nullptr);
    // launch 9: MLP down + gated residual (gate_mlp = chunk 5) -> d_out
    gemm_tc<2><<<dim3(8, ROWS/128), 256, G_SMEM_BYTES>>>(
        hbuf, w2, out, ROWS, DIM, MLPD, mod + 5*DIM, out);
}

// round 14
// speedup vs baseline: 1.4746x; 1.3981x over previous
#include <cuda_runtime.h>
#include <cuda_fp16.h>
#include <math.h>
#include <stdint.h>

#define DIM   1024
#define BT    2
#define NT    2048
#define HEADS 16
#define HD    64
#define MLPD  4096
#define ROWS  (BT*NT)

typedef __half h16;

// ---------------------------------------------------------------------------
// Scratch (static device globals)
// ---------------------------------------------------------------------------
__device__ float g_mod [BT*6*DIM];
__device__ __align__(16) h16 g_xn  [ROWS*DIM];
__device__ __align__(16) h16 g_q   [ROWS*DIM];
__device__ __align__(16) h16 g_k   [ROWS*DIM];
__device__ __align__(16) h16 g_v   [ROWS*DIM];
__device__ __align__(16) h16 g_attn[ROWS*DIM];
__device__ __align__(16) h16 g_h   [(size_t)ROWS*MLPD];
// fp16 weights, transposed to [N][K]: QKV (3M), Wo (1M), W1 (4M), W2 (4M)
__device__ __align__(16) h16 g_wt  [12*1024*1024];

#define W_O (3*1024*1024)
#define W_1 (4*1024*1024)
#define W_2 (8*1024*1024)

// ---------------------------------------------------------------------------
// PTX helpers
// ---------------------------------------------------------------------------
__device__ __forceinline__ uint32_t smaddr(const void* p){
    return (uint32_t)__cvta_generic_to_shared(p);
}
__device__ __forceinline__ void cp16(uint32_t d, const void* s){
    asm volatile("cp.async.cg.shared.global [%0], [%1], 16;\n" :: "r"(d), "l"(s));
}
__device__ __forceinline__ void cp_commit(){
    asm volatile("cp.async.commit_group;\n" ::);
}
__device__ __forceinline__ void cp_wait1(){
    asm volatile("cp.async.wait_group 1;\n" ::);
}
// D(16x8,f32) += A(16x16 f16, row) * B(16x8 f16, col)
__device__ __forceinline__ void mma_h(float* c, const uint32_t* a, const uint32_t* b){
    asm volatile(
        "mma.sync.aligned.m16n8k16.row.col.f32.f16.f16.f32 "
        "{%0,%1,%2,%3}, {%4,%5,%6,%7}, {%8,%9}, {%0,%1,%2,%3};\n"
        : "+f"(c[0]), "+f"(c[1]), "+f"(c[2]), "+f"(c[3])
        : "r"(a[0]), "r"(a[1]), "r"(a[2]), "r"(a[3]),
          "r"(b[0]), "r"(b[1]));
}

// ---------------------------------------------------------------------------
// 0) ONE fused weight prepass: fp32 W[K][N] -> fp16 Wt[N][K] for all 6 mats
// ---------------------------------------------------------------------------
__global__ void __launch_bounds__(256) trans_all(
    const float* __restrict__ Wq, const float* __restrict__ Wk,
    const float* __restrict__ Wv, const float* __restrict__ Wo,
    const float* __restrict__ W1, const float* __restrict__ W2,
    h16* __restrict__ wt)
{
    __shared__ float t[32][33];
    int bid = blockIdx.x;
    const float* src; h16* dst; int K, N, kb, nb;
    if (bid < 4096) {
        int m = bid >> 10, tile = bid & 1023;
        src = (m==0)?Wq:(m==1)?Wk:(m==2)?Wv:Wo;
        dst = wt + (size_t)m*1024*1024;
        K = 1024; N = 1024;
        kb = (tile >> 5)*32; nb = (tile & 31)*32;
    } else if (bid < 8192) {
        int tile = bid - 4096;
        src = W1; dst = wt + W_1; K = 1024; N = 4096;
        kb = (tile >> 7)*32; nb = (tile & 127)*32;
    } else {
        int tile = bid - 8192;
        src = W2; dst = wt + W_2; K = 4096; N = 1024;
        kb = (tile >> 5)*32; nb = (tile & 31)*32;
    }
    int tx = threadIdx.x & 31, ty = threadIdx.x >> 5;
    #pragma unroll
    for (int j = 0; j < 32; j += 8)
        t[ty+j][tx] = src[(size_t)(kb+ty+j)*N + nb + tx];
    __syncthreads();
    #pragma unroll
    for (int j = 0; j < 32; j += 8)
        dst[(size_t)(nb+ty+j)*K + kb + tx] = __float2half(t[tx][ty+j]);
}

// ---------------------------------------------------------------------------
// 1) mod = silu(t_emb) @ ada_W + ada_b
// ---------------------------------------------------------------------------
__global__ void __launch_bounds__(256) silu_mod_kernel(
    const float* __restrict__ t_emb, const float* __restrict__ adaW,
    const float* __restrict__ adab, float* __restrict__ mod)
{
    __shared__ float st[DIM];
    int b = blockIdx.y;
    int j = blockIdx.x * 256 + threadIdx.x;
    for (int i = threadIdx.x; i < DIM; i += 256) {
        float t = t_emb[b*DIM + i];
        st[i] = t / (1.f + __expf(-t));
    }
    __syncthreads();
    float acc = 0.f;
    #pragma unroll 4
    for (int kk = 0; kk < DIM; kk++)
        acc += st[kk] * adaW[(size_t)kk*6*DIM + j];
    mod[b*6*DIM + j] = acc + adab[j];
}

// ---------------------------------------------------------------------------
// 2) LN + adaLN modulation -> fp16
// ---------------------------------------------------------------------------
__global__ void __launch_bounds__(256) ln_mod_kernel(
    const float* __restrict__ x, h16* __restrict__ out,
    const float* __restrict__ g, const float* __restrict__ bb,
    const float* __restrict__ mod, int shift_chunk, int scale_chunk)
{
    int row = blockIdx.x;
    int b   = row >> 11;
    int tid = threadIdx.x;
    const float* xr = x + (size_t)row*DIM;
    float4 xv = *(const float4*)(xr + tid*4);
    float s  = xv.x + xv.y + xv.z + xv.w;
    float s2 = xv.x*xv.x + xv.y*xv.y + xv.z*xv.z + xv.w*xv.w;
    #pragma unroll
    for (int o = 16; o > 0; o >>= 1) {
        s  += __shfl_xor_sync(0xffffffffu, s,  o);
        s2 += __shfl_xor_sync(0xffffffffu, s2, o);
    }
    __shared__ float ws[8], ws2[8];
    __shared__ float smu, srstd;
    int wid = tid >> 5;
    if ((tid & 31) == 0) { ws[wid] = s; ws2[wid] = s2; }
    __syncthreads();
    if (tid == 0) {
        float S = 0.f, S2 = 0.f;
        #pragma unroll
        for (int i = 0; i < 8; i++) { S += ws[i]; S2 += ws2[i]; }
        float mu  = S  * (1.f/DIM);
        float var = S2 * (1.f/DIM) - mu*mu;
        smu = mu; srstd = rsqrtf(var + 1e-5f);
    }
    __syncthreads();
    float mu = smu, rstd = srstd;
    int c = tid*4;
    const float* mb = mod + b*6*DIM;
    float4 gv = *(const float4*)(g  + c);
    float4 bv = *(const float4*)(bb + c);
    float4 sc = *(const float4*)(mb + scale_chunk*DIM + c);
    float4 sh = *(const float4*)(mb + shift_chunk*DIM + c);
    float y0 = ((xv.x-mu)*rstd*gv.x + bv.x)*(1.f+sc.x) + sh.x;
    float y1 = ((xv.y-mu)*rstd*gv.y + bv.y)*(1.f+sc.y) + sh.y;
    float y2 = ((xv.z-mu)*rstd*gv.z + bv.z)*(1.f+sc.z) + sh.z;
    float y3 = ((xv.w-mu)*rstd*gv.w + bv.w)*(1.f+sc.w) + sh.w;
    h16* o = out + (size_t)row*DIM + c;
    *(__half2*)o       = __floats2half2_rn(y0, y1);
    *(__half2*)(o + 2) = __floats2half2_rn(y2, y3);
}

// ---------------------------------------------------------------------------
// fp16 GEMM: Out(M,Nc) = A(M,K) @ W(K,Nc), W given transposed Wt[Nc][K] fp16.
//   BM=BN=128, BK=64, 8 warps (4M x 2N), warp 32x64, m16n8k16, 2 CTA/SM.
//   EPI: 0 = fp16 store into one of 3 outputs (QKV, grid.x=24)
//        1 = exact GELU -> fp16
//        2 = res + gate*acc -> fp32 (d_out)
// ---------------------------------------------------------------------------
#define GTILE (128*72)                 // halves per tile
#define GBUF  (2*GTILE)
#define GBUF_BYTES (GBUF*2)            // 36864
#define G_SMEM_BYTES (2*GBUF_BYTES)    // 73728

template<int EPI>
__global__ void __launch_bounds__(256, 2) gemm_h(
    const h16* __restrict__ A, const h16* __restrict__ Wt,
    int K, int Nc,
    h16* __restrict__ o16a, h16* __restrict__ o16b, h16* __restrict__ o16c,
    float* __restrict__ ofp,
    const float* __restrict__ gate, const float* __restrict__ res)
{
    extern __shared__ h16 smh[];
    const int tid  = threadIdx.x;
    const int lane = tid & 31, warp = tid >> 5;
    const int grp  = lane >> 2, tig = lane & 3;
    const int wm   = warp & 3,  wn  = warp >> 2;
    const int m0   = blockIdx.y * 128;
    const int n0g  = blockIdx.x * 128;
    const uint32_t smb = smaddr(smh);
    const int nk = K >> 6;

    float acc[2][8][4];
    #pragma unroll
    for (int i = 0; i < 2; i++)
        #pragma unroll
        for (int j = 0; j < 8; j++)
            #pragma unroll
            for (int t = 0; t < 4; t++) acc[i][j][t] = 0.f;

    auto prefetch = [&](int kc, int bufi){
        uint32_t base = smb + bufi*GBUF_BYTES;
        #pragma unroll
        for (int i = 0; i < 4; i++) {
            int idx = tid + i*256;
            int r = idx >> 3, c8 = (idx & 7) * 8;
            cp16(base + (uint32_t)(r*72 + c8)*2u,
                 A + (size_t)(m0 + r)*K + kc*64 + c8);
        }
        #pragma unroll
        for (int i = 0; i < 4; i++) {
            int idx = tid + i*256;
            int r = idx >> 3, c8 = (idx & 7) * 8;
            cp16(base + (uint32_t)(GTILE + r*72 + c8)*2u,
                 Wt + (size_t)(n0g + r)*K + kc*64 + c8);
        }
        cp_commit();
    };

    prefetch(0, 0);
    if (nk > 1) prefetch(1, 1); else cp_commit();

    int buf = 0;
    for (int kc = 0; kc < nk; kc++) {
        cp_wait1();
        __syncthreads();
        const h16* As = smh + buf*GBUF;
        const h16* Bs = As + GTILE;
        #pragma unroll
        for (int kk = 0; kk < 64; kk += 16) {
            uint32_t a[2][4], b[8][2];
            #pragma unroll
            for (int ma = 0; ma < 2; ma++) {
                int r = wm*32 + ma*16 + grp;
                a[ma][0] = *(const uint32_t*)&As[r    *72 + kk + 2*tig];
                a[ma][1] = *(const uint32_t*)&As[(r+8)*72 + kk + 2*tig];
                a[ma][2] = *(const uint32_t*)&As[r    *72 + kk + 2*tig + 8];
                a[ma][3] = *(const uint32_t*)&As[(r+8)*72 + kk + 2*tig + 8];
            }
            #pragma unroll
            for (int nb = 0; nb < 8; nb++) {
                int c = wn*64 + nb*8 + grp;
                b[nb][0] = *(const uint32_t*)&Bs[c*72 + kk + 2*tig];
                b[nb][1] = *(const uint32_t*)&Bs[c*72 + kk + 2*tig + 8];
            }
            #pragma unroll
            for (int ma = 0; ma < 2; ma++)
                #pragma unroll
                for (int nb = 0; nb < 8; nb++)
                    mma_h(acc[ma][nb], a[ma], b[nb]);
        }
        __syncthreads();
        if (kc + 2 < nk) prefetch(kc + 2, buf);
        else cp_commit();
        buf ^= 1;
    }

    #pragma unroll
    for (int ma = 0; ma < 2; ma++) {
        int r0 = m0 + wm*32 + ma*16 + grp;
        #pragma unroll
        for (int nb = 0; nb < 8; nb++) {
            int cl = wn*64 + nb*8 + 2*tig;
            float o0 = acc[ma][nb][0], o1 = acc[ma][nb][1];
            float o2 = acc[ma][nb][2], o3 = acc[ma][nb][3];
            if (EPI == 0) {
                int mat = blockIdx.x >> 3;
                h16* O = (mat == 0) ? o16a : (mat == 1) ? o16b : o16c;
                int c = ((blockIdx.x & 7) * 128) + cl;
                *(__half2*)(O + (size_t)r0    *DIM + c) = __floats2half2_rn(o0, o1);
                *(__half2*)(O + (size_t)(r0+8)*DIM + c) = __floats2half2_rn(o2, o3);
            } else if (EPI == 1) {
                int c = n0g + cl;
                o0 = 0.5f*o0*(1.f + erff(o0*0.70710678f));
                o1 = 0.5f*o1*(1.f + erff(o1*0.70710678f));
                o2 = 0.5f*o2*(1.f + erff(o2*0.70710678f));
                o3 = 0.5f*o3*(1.f + erff(o3*0.70710678f));
                *(__half2*)(o16a + (size_t)r0    *Nc + c) = __floats2half2_rn(o0, o1);
                *(__half2*)(o16a + (size_t)(r0+8)*Nc + c) = __floats2half2_rn(o2, o3);
            } else {
                int c = n0g + cl;
                int bi = r0 >> 11;
                float2 g2 = *(const float2*)(gate + bi*6*DIM + c);
                float2 ra = *(const float2*)(res + (size_t)r0    *Nc + c);
                float2 rb = *(const float2*)(res + (size_t)(r0+8)*Nc + c);
                o0 = ra.x + g2.x*o0; o1 = ra.y + g2.y*o1;
                o2 = rb.x + g2.x*o2; o3 = rb.y + g2.y*o3;
                *(float2*)(ofp + (size_t)r0    *Nc + c) = make_float2(o0, o1);
                *(float2*)(ofp + (size_t)(r0+8)*Nc + c) = make_float2(o2, o3);
            }
        }
    }
}

// ---------------------------------------------------------------------------
// 4) RoPE on fp16 q,k (fp32 math inside)
// ---------------------------------------------------------------------------
__global__ void __launch_bounds__(256) rope_kernel(h16* __restrict__ q,
                                                   h16* __restrict__ k)
{
    int idx = blockIdx.x*256 + threadIdx.x;
    int n = (idx >> 4) & (NT-1);
    float cs[32], sn[32];
    #pragma unroll
    for (int j = 0; j < 32; j++) {
        float invf = expf((float)j * -0.2878231366f);
        float ang  = (float)n * invf;
        sincosf(ang, &sn[j], &cs[j]);
    }
    h16* ptrs[2]; ptrs[0] = q + (size_t)idx*64; ptrs[1] = k + (size_t)idx*64;
    #pragma unroll
    for (int tpi = 0; tpi < 2; tpi++) {
        h16* p = ptrs[tpi];
        float buf[64];
        #pragma unroll
        for (int u = 0; u < 16; u++) {
            __half2 t = *(const __half2*)(p + u*4);
            __half2 t2 = *(const __half2*)(p + u*4 + 2);
            float2 f = __half22float2(t), f2 = __half22float2(t2);
            buf[u*4+0] = f.x;  buf[u*4+1] = f.y;
            buf[u*4+2] = f2.x; buf[u*4+3] = f2.y;
        }
        #pragma unroll
        for (int t = 0; t < 8; t++) {
            float l0 = buf[4*t+0]*cs[4*t+0] - buf[8*t+1]*sn[4*t+0];
            float l1 = buf[4*t+1]*cs[4*t+1] - buf[8*t+3]*sn[4*t+1];
            float l2 = buf[4*t+2]*cs[4*t+2] - buf[8*t+5]*sn[4*t+2];
            float l3 = buf[4*t+3]*cs[4*t+3] - buf[8*t+7]*sn[4*t+3];
            float h0 = buf[32+4*t+0]*cs[4*t+0] + buf[8*t+0]*sn[4*t+0];
            float h1 = buf[32+4*t+1]*cs[4*t+1] + buf[8*t+2]*sn[4*t+1];
            float h2 = buf[32+4*t+2]*cs[4*t+2] + buf[8*t+4]*sn[4*t+2];
            float h3 = buf[32+4*t+3]*cs[4*t+3] + buf[8*t+6]*sn[4*t+3];
            *(__half2*)(p + 4*t)          = __floats2half2_rn(l0, l1);
            *(__half2*)(p + 4*t + 2)      = __floats2half2_rn(l2, l3);
            *(__half2*)(p + 32 + 4*t)     = __floats2half2_rn(h0, h1);
            *(__half2*)(p + 32 + 4*t + 2) = __floats2half2_rn(h2, h3);
        }
    }
}

// ---------------------------------------------------------------------------
// 5) Flash attention, fp16 m16n8k16. Q tile 128, 8 warps x 16 rows.
// ---------------------------------------------------------------------------
#define FQ 0
#define FK (128*72)
#define FP (FK + 64*72)
#define FV (FP + 128*72)
#define F_SMEM_BYTES ((FV + 64*72)*2)

__global__ void __launch_bounds__(256) flash_h(
    const h16* __restrict__ q, const h16* __restrict__ k,
    const h16* __restrict__ v, h16* __restrict__ o)
{
    extern __shared__ h16 smh[];
    h16* Qs = smh + FQ;
    h16* Ks = smh + FK;
    h16* Ps = smh + FP;
    h16* Vt = smh + FV;

    const int qt = blockIdx.x, bh = blockIdx.y;
    const int b = bh >> 4, h = bh & 15;
    const int tid = threadIdx.x;
    const int lane = tid & 31, warp = tid >> 5;
    const int grp = lane >> 2, tig = lane & 3;
    const int wrow = warp * 16;
    const h16* qb = q + (size_t)b*NT*DIM + h*HD;
    const h16* kb = k + (size_t)b*NT*DIM + h*HD;
    const h16* vb = v + (size_t)b*NT*DIM + h*HD;

    const __half2 mk = __floats2half2_rn(0.125f, 0.125f);
    #pragma unroll
    for (int i = 0; i < 4; i++) {
        int idx = tid + i*256;
        int r = idx >> 3, c8 = (idx & 7) * 8;
        uint4 u = *(const uint4*)(qb + (size_t)(qt*128 + r)*DIM + c8);
        __half2* hp = (__half2*)&u;
        hp[0] = __hmul2(hp[0], mk); hp[1] = __hmul2(hp[1], mk);
        hp[2] = __hmul2(hp[2], mk); hp[3] = __hmul2(hp[3], mk);
        *(uint4*)&Qs[r*72 + c8] = u;
    }

    float O[8][4];
    #pragma unroll
    for (int i = 0; i < 8; i++)
        #pragma unroll
        for (int j = 0; j < 4; j++) O[i][j] = 0.f;
    float m0 = -1e30f, m1 = -1e30f, l0 = 0.f, l1 = 0.f;

    for (int kt = 0; kt < NT/64; kt++) {
        __syncthreads();
        #pragma unroll
        for (int i = 0; i < 2; i++) {
            int idx = tid + i*256;
            int r = idx >> 3, c8 = (idx & 7) * 8;
            uint4 u = *(const uint4*)(kb + (size_t)(kt*64 + r)*DIM + c8);
            *(uint4*)&Ks[r*72 + c8] = u;
        }
        #pragma unroll
        for (int i = 0; i < 2; i++) {
            int idx = tid + i*256;
            int j = idx >> 3, d8 = (idx & 7) * 8;
            uint4 u = *(const uint4*)(vb + (size_t)(kt*64 + j)*DIM + d8);
            const h16* t = (const h16*)&u;
            #pragma unroll
            for (int u8 = 0; u8 < 8; u8++)
                Vt[(d8+u8)*72 + j] = t[u8];
        }
        __syncthreads();

        float s[8][4];
        #pragma unroll
        for (int i = 0; i < 8; i++)
            #pragma unroll
            for (int j = 0; j < 4; j++) s[i][j] = 0.f;
        #pragma unroll
        for (int kk = 0; kk < 64; kk += 16) {
            uint32_t a[4];
            a[0] = *(const uint32_t*)&Qs[(wrow+grp  )*72 + kk + 2*tig];
            a[1] = *(const uint32_t*)&Qs[(wrow+grp+8)*72 + kk + 2*tig];
            a[2] = *(const uint32_t*)&Qs[(wrow+grp  )*72 + kk + 2*tig + 8];
            a[3] = *(const uint32_t*)&Qs[(wrow+grp+8)*72 + kk + 2*tig + 8];
            #pragma unroll
            for (int nb = 0; nb < 8; nb++) {
                int c = nb*8 + grp;
                uint32_t bb[2];
                bb[0] = *(const uint32_t*)&Ks[c*72 + kk + 2*tig];
                bb[1] = *(const uint32_t*)&Ks[c*72 + kk + 2*tig + 8];
                mma_h(s[nb], a, bb);
            }
        }

        float mx0 = -1e30f, mx1 = -1e30f;
        #pragma unroll
        for (int nb = 0; nb < 8; nb++) {
            mx0 = fmaxf(mx0, fmaxf(s[nb][0], s[nb][1]));
            mx1 = fmaxf(mx1, fmaxf(s[nb][2], s[nb][3]));
        }
        mx0 = fmaxf(mx0, __shfl_xor_sync(0xffffffffu, mx0, 1));
        mx0 = fmaxf(mx0, __shfl_xor_sync(0xffffffffu, mx0, 2));
        mx1 = fmaxf(mx1, __shfl_xor_sync(0xffffffffu, mx1, 1));
        mx1 = fmaxf(mx1, __shfl_xor_sync(0xffffffffu, mx1, 2));
        float nm0 = fmaxf(m0, mx0), nm1 = fmaxf(m1, mx1);
        float a0 = __expf(m0 - nm0), a1 = __expf(m1 - nm1);
        float rs0 = 0.f, rs1 = 0.f;
        #pragma unroll
        for (int nb = 0; nb < 8; nb++) {
            __half2 hp0 = __floats2half2_rn(__expf(s[nb][0] - nm0),
                                            __expf(s[nb][1] - nm0));
            __half2 hp1 = __floats2half2_rn(__expf(s[nb][2] - nm1),
                                            __expf(s[nb][3] - nm1));
            float2 f0 = __half22float2(hp0), f1 = __half22float2(hp1);
            rs0 += f0.x + f0.y; rs1 += f1.x + f1.y;
            *(__half2*)&Ps[(wrow+grp  )*72 + nb*8 + 2*tig] = hp0;
            *(__half2*)&Ps[(wrow+grp+8)*72 + nb*8 + 2*tig] = hp1;
            O[nb][0] *= a0; O[nb][1] *= a0;
            O[nb][2] *= a1; O[nb][3] *= a1;
        }
        rs0 += __shfl_xor_sync(0xffffffffu, rs0, 1);
        rs0 += __shfl_xor_sync(0xffffffffu, rs0, 2);
        rs1 += __shfl_xor_sync(0xffffffffu, rs1, 1);
        rs1 += __shfl_xor_sync(0xffffffffu, rs1, 2);
        l0 = l0*a0 + rs0; l1 = l1*a1 + rs1;
        m0 = nm0; m1 = nm1;
        __syncwarp();

        #pragma unroll
        for (int kk = 0; kk < 64; kk += 16) {
            uint32_t a[4];
            a[0] = *(const uint32_t*)&Ps[(wrow+grp  )*72 + kk + 2*tig];
            a[1] = *(const uint32_t*)&Ps[(wrow+grp+8)*72 + kk + 2*tig];
            a[2] = *(const uint32_t*)&Ps[(wrow+grp  )*72 + kk + 2*tig + 8];
            a[3] = *(const uint32_t*)&Ps[(wrow+grp+8)*72 + kk + 2*tig + 8];
            #pragma unroll
            for (int nb = 0; nb < 8; nb++) {
                int d = nb*8 + grp;
                uint32_t bb[2];
                bb[0] = *(const uint32_t*)&Vt[d*72 + kk + 2*tig];
                bb[1] = *(const uint32_t*)&Vt[d*72 + kk + 2*tig + 8];
                mma_h(O[nb], a, bb);
            }
        }
        __syncwarp();
    }

    float i0 = 1.f/l0, i1 = 1.f/l1;
    int row = qt*128 + wrow + grp;
    #pragma unroll
    for (int nb = 0; nb < 8; nb++) {
        size_t off = (size_t)(b*NT + row)*DIM + h*HD + nb*8 + 2*tig;
        *(__half2*)(o + off)         = __floats2half2_rn(O[nb][0]*i0, O[nb][1]*i0);
        *(__half2*)(o + off + 8*DIM) = __floats2half2_rn(O[nb][2]*i1, O[nb][3]*i1);
    }
}

// ---------------------------------------------------------------------------
// Host launcher (flash at launch index 5 for ncu -s 5)
// ---------------------------------------------------------------------------
extern "C" void kernel_launch(void* const* d_in, const int* in_sizes, int n_in,
                              void* d_out, int out_size)
{
    const float* x       = (const float*)d_in[0];
    const float* t_emb   = (const float*)d_in[1];
    const float* norm1_g = (const float*)d_in[2];
    const float* norm1_b = (const float*)d_in[3];
    const float* Wq      = (const float*)d_in[4];
    const float* Wk      = (const float*)d_in[5];
    const float* Wv      = (const float*)d_in[6];
    const float* Wo      = (const float*)d_in[7];
    const float* norm2_g = (const float*)d_in[8];
    const float* norm2_b = (const float*)d_in[9];
    const float* W1      = (const float*)d_in[10];
    const float* W2      = (const float*)d_in[11];
    const float* ada_W   = (const float*)d_in[12];
    const float* ada_b   = (const float*)d_in[13];
    float* out = (float*)d_out;

    float *mod;
    h16 *xn, *q, *k, *v, *attn, *hbuf, *wt;
    cudaGetSymbolAddress((void**)&mod,  g_mod);
    cudaGetSymbolAddress((void**)&xn,   g_xn);
    cudaGetSymbolAddress((void**)&q,    g_q);
    cudaGetSymbolAddress((void**)&k,    g_k);
    cudaGetSymbolAddress((void**)&v,    g_v);
    cudaGetSymbolAddress((void**)&attn, g_attn);
    cudaGetSymbolAddress((void**)&hbuf, g_h);
    cudaGetSymbolAddress((void**)&wt,   g_wt);

    cudaFuncSetAttribute(gemm_h<0>, cudaFuncAttributeMaxDynamicSharedMemorySize, G_SMEM_BYTES);
    cudaFuncSetAttribute(gemm_h<1>, cudaFuncAttributeMaxDynamicSharedMemorySize, G_SMEM_BYTES);
    cudaFuncSetAttribute(gemm_h<2>, cudaFuncAttributeMaxDynamicSharedMemorySize, G_SMEM_BYTES);
    cudaFuncSetAttribute(flash_h,   cudaFuncAttributeMaxDynamicSharedMemorySize, F_SMEM_BYTES);

    // launch 0: fused weight transpose -> fp16 [N][K]
    trans_all<<<12288, 256>>>(Wq, Wk, Wv, Wo, W1, W2, wt);
    // launch 1: adaLN modulation
    silu_mod_kernel<<<dim3(24, BT), 256>>>(t_emb, ada_W, ada_b, mod);
    // launch 2: LN1 + modulate -> fp16
    ln_mod_kernel<<<ROWS, 256>>>(x, xn, norm1_g, norm1_b, mod, 0, 1);
    // launch 3: fused QKV (Wt rows 0..3071)
    gemm_h<0><<<dim3(24, ROWS/128), 256, G_SMEM_BYTES>>>(
        xn, wt, DIM, DIM, q, k, v, nullptr, nullptr, nullptr);
    // launch 4: RoPE
    rope_kernel<<<(BT*NT*HEADS)/256, 256>>>(q, k);
    // launch 5: attention
    flash_h<<<dim3(NT/128, BT*HEADS), 256, F_SMEM_BYTES>>>(q, k, v, attn);
    // launch 6: out proj + gated residual (gate_msa = chunk 2) -> d_out
    gemm_h<2><<<dim3(8, ROWS/128), 256, G_SMEM_BYTES>>>(
        attn, wt + W_O, DIM, DIM, nullptr, nullptr, nullptr,
        out, mod + 2*DIM, x);
    // launch 7: LN2 + modulate -> fp16
    ln_mod_kernel<<<ROWS, 256>>>(out, xn, norm2_g, norm2_b, mod, 3, 4);
    // launch 8: MLP up + exact GELU -> fp16
    gemm_h<1><<<dim3(32, ROWS/128), 256, G_SMEM_BYTES>>>(
        xn, wt + W_1, DIM, MLPD, hbuf, nullptr, nullptr,
        nullptr, nullptr, nullptr);
    // launch 9: MLP down + gated residual (gate_mlp = chunk 5) -> d_out
    //           *** grid.x = 8 (BN=128, Nc=1024) — this was the R12 bug ***
    gemm_h<2><<<dim3(8, ROWS/128), 256, G_SMEM_BYTES>>>(
        hbuf, wt + W_2, MLPD, DIM, nullptr, nullptr, nullptr,
        out, mod + 5*DIM, out);
}

// round 15
// speedup vs baseline: 1.5960x; 1.0823x over previous
#include <cuda_runtime.h>
#include <cuda_fp16.h>
#include <math.h>
#include <stdint.h>

#define DIM   1024
#define BT    2
#define NT    2048
#define HEADS 16
#define HD    64
#define MLPD  4096
#define ROWS  (BT*NT)

typedef __half h16;

// ---------------------------------------------------------------------------
// Scratch (static device globals)
// ---------------------------------------------------------------------------
__device__ float g_mod [BT*6*DIM];
__device__ __align__(16) h16 g_xn  [ROWS*DIM];
__device__ __align__(16) h16 g_q   [ROWS*DIM];
__device__ __align__(16) h16 g_k   [ROWS*DIM];
__device__ __align__(16) h16 g_v   [ROWS*DIM];
__device__ __align__(16) h16 g_attn[ROWS*DIM];
__device__ __align__(16) h16 g_h   [(size_t)ROWS*MLPD];
// fp16 weights, transposed to [N][K]: QKV (3M), Wo (1M), W1 (4M), W2 (4M)
__device__ __align__(16) h16 g_wt  [12*1024*1024];

#define W_O (3*1024*1024)
#define W_1 (4*1024*1024)
#define W_2 (8*1024*1024)

// ---------------------------------------------------------------------------
// PTX helpers
// ---------------------------------------------------------------------------
__device__ __forceinline__ uint32_t smaddr(const void* p){
    return (uint32_t)__cvta_generic_to_shared(p);
}
__device__ __forceinline__ void cp16(uint32_t d, const void* s){
    asm volatile("cp.async.cg.shared.global [%0], [%1], 16;\n" :: "r"(d), "l"(s));
}
__device__ __forceinline__ void cp_commit(){
    asm volatile("cp.async.commit_group;\n" ::);
}
__device__ __forceinline__ void cp_wait1(){
    asm volatile("cp.async.wait_group 1;\n" ::);
}
// D(16x8,f32) += A(16x16 f16, row) * B(16x8 f16, col)
__device__ __forceinline__ void mma_h(float* c, const uint32_t* a, const uint32_t* b){
    asm volatile(
        "mma.sync.aligned.m16n8k16.row.col.f32.f16.f16.f32 "
        "{%0,%1,%2,%3}, {%4,%5,%6,%7}, {%8,%9}, {%0,%1,%2,%3};\n"
        : "+f"(c[0]), "+f"(c[1]), "+f"(c[2]), "+f"(c[3])
        : "r"(a[0]), "r"(a[1]), "r"(a[2]), "r"(a[3]),
          "r"(b[0]), "r"(b[1]));
}

// ---------------------------------------------------------------------------
// 0) ONE fused weight prepass: fp32 W[K][N] -> fp16 Wt[N][K] for all 6 mats
// ---------------------------------------------------------------------------
__global__ void __launch_bounds__(256) trans_all(
    const float* __restrict__ Wq, const float* __restrict__ Wk,
    const float* __restrict__ Wv, const float* __restrict__ Wo,
    const float* __restrict__ W1, const float* __restrict__ W2,
    h16* __restrict__ wt)
{
    __shared__ float t[32][33];
    int bid = blockIdx.x;
    const float* src; h16* dst; int K, N, kb, nb;
    if (bid < 4096) {
        int m = bid >> 10, tile = bid & 1023;
        src = (m==0)?Wq:(m==1)?Wk:(m==2)?Wv:Wo;
        dst = wt + (size_t)m*1024*1024;
        K = 1024; N = 1024;
        kb = (tile >> 5)*32; nb = (tile & 31)*32;
    } else if (bid < 8192) {
        int tile = bid - 4096;
        src = W1; dst = wt + W_1; K = 1024; N = 4096;
        kb = (tile >> 7)*32; nb = (tile & 127)*32;
    } else {
        int tile = bid - 8192;
        src = W2; dst = wt + W_2; K = 4096; N = 1024;
        kb = (tile >> 5)*32; nb = (tile & 31)*32;
    }
    int tx = threadIdx.x & 31, ty = threadIdx.x >> 5;
    #pragma unroll
    for (int j = 0; j < 32; j += 8)
        t[ty+j][tx] = src[(size_t)(kb+ty+j)*N + nb + tx];
    __syncthreads();
    #pragma unroll
    for (int j = 0; j < 32; j += 8)
        dst[(size_t)(nb+ty+j)*K + kb + tx] = __float2half(t[tx][ty+j]);
}

// ---------------------------------------------------------------------------
// 1) mod = silu(t_emb) @ ada_W + ada_b
// ---------------------------------------------------------------------------
__global__ void __launch_bounds__(256) silu_mod_kernel(
    const float* __restrict__ t_emb, const float* __restrict__ adaW,
    const float* __restrict__ adab, float* __restrict__ mod)
{
    __shared__ float st[DIM];
    int b = blockIdx.y;
    int j = blockIdx.x * 256 + threadIdx.x;
    for (int i = threadIdx.x; i < DIM; i += 256) {
        float t = t_emb[b*DIM + i];
        st[i] = t / (1.f + __expf(-t));
    }
    __syncthreads();
    float acc = 0.f;
    #pragma unroll 4
    for (int kk = 0; kk < DIM; kk++)
        acc += st[kk] * adaW[(size_t)kk*6*DIM + j];
    mod[b*6*DIM + j] = acc + adab[j];
}

// ---------------------------------------------------------------------------
// 2) LN + adaLN modulation -> fp16
// ---------------------------------------------------------------------------
__global__ void __launch_bounds__(256) ln_mod_kernel(
    const float* __restrict__ x, h16* __restrict__ out,
    const float* __restrict__ g, const float* __restrict__ bb,
    const float* __restrict__ mod, int shift_chunk, int scale_chunk)
{
    int row = blockIdx.x;
    int b   = row >> 11;
    int tid = threadIdx.x;
    const float* xr = x + (size_t)row*DIM;
    float4 xv = *(const float4*)(xr + tid*4);
    float s  = xv.x + xv.y + xv.z + xv.w;
    float s2 = xv.x*xv.x + xv.y*xv.y + xv.z*xv.z + xv.w*xv.w;
    #pragma unroll
    for (int o = 16; o > 0; o >>= 1) {
        s  += __shfl_xor_sync(0xffffffffu, s,  o);
        s2 += __shfl_xor_sync(0xffffffffu, s2, o);
    }
    __shared__ float ws[8], ws2[8];
    __shared__ float smu, srstd;
    int wid = tid >> 5;
    if ((tid & 31) == 0) { ws[wid] = s; ws2[wid] = s2; }
    __syncthreads();
    if (tid == 0) {
        float S = 0.f, S2 = 0.f;
        #pragma unroll
        for (int i = 0; i < 8; i++) { S += ws[i]; S2 += ws2[i]; }
        float mu  = S  * (1.f/DIM);
        float var = S2 * (1.f/DIM) - mu*mu;
        smu = mu; srstd = rsqrtf(var + 1e-5f);
    }
    __syncthreads();
    float mu = smu, rstd = srstd;
    int c = tid*4;
    const float* mb = mod + b*6*DIM;
    float4 gv = *(const float4*)(g  + c);
    float4 bv = *(const float4*)(bb + c);
    float4 sc = *(const float4*)(mb + scale_chunk*DIM + c);
    float4 sh = *(const float4*)(mb + shift_chunk*DIM + c);
    float y0 = ((xv.x-mu)*rstd*gv.x + bv.x)*(1.f+sc.x) + sh.x;
    float y1 = ((xv.y-mu)*rstd*gv.y + bv.y)*(1.f+sc.y) + sh.y;
    float y2 = ((xv.z-mu)*rstd*gv.z + bv.z)*(1.f+sc.z) + sh.z;
    float y3 = ((xv.w-mu)*rstd*gv.w + bv.w)*(1.f+sc.w) + sh.w;
    h16* o = out + (size_t)row*DIM + c;
    *(__half2*)o       = __floats2half2_rn(y0, y1);
    *(__half2*)(o + 2) = __floats2half2_rn(y2, y3);
}

// ---------------------------------------------------------------------------
// fp16 GEMM (unchanged from R13-pass): BM=BN=128, BK=64, warp 32x64, 2 CTA/SM
// ---------------------------------------------------------------------------
#define GTILE (128*72)
#define GBUF  (2*GTILE)
#define GBUF_BYTES (GBUF*2)
#define G_SMEM_BYTES (2*GBUF_BYTES)

template<int EPI>
__global__ void __launch_bounds__(256, 2) gemm_h(
    const h16* __restrict__ A, const h16* __restrict__ Wt,
    int K, int Nc,
    h16* __restrict__ o16a, h16* __restrict__ o16b, h16* __restrict__ o16c,
    float* __restrict__ ofp,
    const float* __restrict__ gate, const float* __restrict__ res)
{
    extern __shared__ h16 smh[];
    const int tid  = threadIdx.x;
    const int lane = tid & 31, warp = tid >> 5;
    const int grp  = lane >> 2, tig = lane & 3;
    const int wm   = warp & 3,  wn  = warp >> 2;
    const int m0   = blockIdx.y * 128;
    const int n0g  = blockIdx.x * 128;
    const uint32_t smb = smaddr(smh);
    const int nk = K >> 6;

    float acc[2][8][4];
    #pragma unroll
    for (int i = 0; i < 2; i++)
        #pragma unroll
        for (int j = 0; j < 8; j++)
            #pragma unroll
            for (int t = 0; t < 4; t++) acc[i][j][t] = 0.f;

    auto prefetch = [&](int kc, int bufi){
        uint32_t base = smb + bufi*GBUF_BYTES;
        #pragma unroll
        for (int i = 0; i < 4; i++) {
            int idx = tid + i*256;
            int r = idx >> 3, c8 = (idx & 7) * 8;
            cp16(base + (uint32_t)(r*72 + c8)*2u,
                 A + (size_t)(m0 + r)*K + kc*64 + c8);
        }
        #pragma unroll
        for (int i = 0; i < 4; i++) {
            int idx = tid + i*256;
            int r = idx >> 3, c8 = (idx & 7) * 8;
            cp16(base + (uint32_t)(GTILE + r*72 + c8)*2u,
                 Wt + (size_t)(n0g + r)*K + kc*64 + c8);
        }
        cp_commit();
    };

    prefetch(0, 0);
    if (nk > 1) prefetch(1, 1); else cp_commit();

    int buf = 0;
    for (int kc = 0; kc < nk; kc++) {
        cp_wait1();
        __syncthreads();
        const h16* As = smh + buf*GBUF;
        const h16* Bs = As + GTILE;
        #pragma unroll
        for (int kk = 0; kk < 64; kk += 16) {
            uint32_t a[2][4], b[8][2];
            #pragma unroll
            for (int ma = 0; ma < 2; ma++) {
                int r = wm*32 + ma*16 + grp;
                a[ma][0] = *(const uint32_t*)&As[r    *72 + kk + 2*tig];
                a[ma][1] = *(const uint32_t*)&As[(r+8)*72 + kk + 2*tig];
                a[ma][2] = *(const uint32_t*)&As[r    *72 + kk + 2*tig + 8];
                a[ma][3] = *(const uint32_t*)&As[(r+8)*72 + kk + 2*tig + 8];
            }
            #pragma unroll
            for (int nb = 0; nb < 8; nb++) {
                int c = wn*64 + nb*8 + grp;
                b[nb][0] = *(const uint32_t*)&Bs[c*72 + kk + 2*tig];
                b[nb][1] = *(const uint32_t*)&Bs[c*72 + kk + 2*tig + 8];
            }
            #pragma unroll
            for (int ma = 0; ma < 2; ma++)
                #pragma unroll
                for (int nb = 0; nb < 8; nb++)
                    mma_h(acc[ma][nb], a[ma], b[nb]);
        }
        __syncthreads();
        if (kc + 2 < nk) prefetch(kc + 2, buf);
        else cp_commit();
        buf ^= 1;
    }

    #pragma unroll
    for (int ma = 0; ma < 2; ma++) {
        int r0 = m0 + wm*32 + ma*16 + grp;
        #pragma unroll
        for (int nb = 0; nb < 8; nb++) {
            int cl = wn*64 + nb*8 + 2*tig;
            float o0 = acc[ma][nb][0], o1 = acc[ma][nb][1];
            float o2 = acc[ma][nb][2], o3 = acc[ma][nb][3];
            if (EPI == 0) {
                int mat = blockIdx.x >> 3;
                h16* O = (mat == 0) ? o16a : (mat == 1) ? o16b : o16c;
                int c = ((blockIdx.x & 7) * 128) + cl;
                *(__half2*)(O + (size_t)r0    *DIM + c) = __floats2half2_rn(o0, o1);
                *(__half2*)(O + (size_t)(r0+8)*DIM + c) = __floats2half2_rn(o2, o3);
            } else if (EPI == 1) {
                int c = n0g + cl;
                o0 = 0.5f*o0*(1.f + erff(o0*0.70710678f));
                o1 = 0.5f*o1*(1.f + erff(o1*0.70710678f));
                o2 = 0.5f*o2*(1.f + erff(o2*0.70710678f));
                o3 = 0.5f*o3*(1.f + erff(o3*0.70710678f));
                *(__half2*)(o16a + (size_t)r0    *Nc + c) = __floats2half2_rn(o0, o1);
                *(__half2*)(o16a + (size_t)(r0+8)*Nc + c) = __floats2half2_rn(o2, o3);
            } else {
                int c = n0g + cl;
                int bi = r0 >> 11;
                float2 g2 = *(const float2*)(gate + bi*6*DIM + c);
                float2 ra = *(const float2*)(res + (size_t)r0    *Nc + c);
                float2 rb = *(const float2*)(res + (size_t)(r0+8)*Nc + c);
                o0 = ra.x + g2.x*o0; o1 = ra.y + g2.y*o1;
                o2 = rb.x + g2.x*o2; o3 = rb.y + g2.y*o3;
                *(float2*)(ofp + (size_t)r0    *Nc + c) = make_float2(o0, o1);
                *(float2*)(ofp + (size_t)(r0+8)*Nc + c) = make_float2(o2, o3);
            }
        }
    }
}

// ---------------------------------------------------------------------------
// 4) RoPE on fp16 q,k (fp32 math inside)
// ---------------------------------------------------------------------------
__global__ void __launch_bounds__(256) rope_kernel(h16* __restrict__ q,
                                                   h16* __restrict__ k)
{
    int idx = blockIdx.x*256 + threadIdx.x;
    int n = (idx >> 4) & (NT-1);
    float cs[32], sn[32];
    #pragma unroll
    for (int j = 0; j < 32; j++) {
        float invf = expf((float)j * -0.2878231366f);
        float ang  = (float)n * invf;
        sincosf(ang, &sn[j], &cs[j]);
    }
    h16* ptrs[2]; ptrs[0] = q + (size_t)idx*64; ptrs[1] = k + (size_t)idx*64;
    #pragma unroll
    for (int tpi = 0; tpi < 2; tpi++) {
        h16* p = ptrs[tpi];
        float buf[64];
        #pragma unroll
        for (int u = 0; u < 16; u++) {
            __half2 t = *(const __half2*)(p + u*4);
            __half2 t2 = *(const __half2*)(p + u*4 + 2);
            float2 f = __half22float2(t), f2 = __half22float2(t2);
            buf[u*4+0] = f.x;  buf[u*4+1] = f.y;
            buf[u*4+2] = f2.x; buf[u*4+3] = f2.y;
        }
        #pragma unroll
        for (int t = 0; t < 8; t++) {
            float l0 = buf[4*t+0]*cs[4*t+0] - buf[8*t+1]*sn[4*t+0];
            float l1 = buf[4*t+1]*cs[4*t+1] - buf[8*t+3]*sn[4*t+1];
            float l2 = buf[4*t+2]*cs[4*t+2] - buf[8*t+5]*sn[4*t+2];
            float l3 = buf[4*t+3]*cs[4*t+3] - buf[8*t+7]*sn[4*t+3];
            float h0 = buf[32+4*t+0]*cs[4*t+0] + buf[8*t+0]*sn[4*t+0];
            float h1 = buf[32+4*t+1]*cs[4*t+1] + buf[8*t+2]*sn[4*t+1];
            float h2 = buf[32+4*t+2]*cs[4*t+2] + buf[8*t+4]*sn[4*t+2];
            float h3 = buf[32+4*t+3]*cs[4*t+3] + buf[8*t+6]*sn[4*t+3];
            *(__half2*)(p + 4*t)          = __floats2half2_rn(l0, l1);
            *(__half2*)(p + 4*t + 2)      = __floats2half2_rn(l2, l3);
            *(__half2*)(p + 32 + 4*t)     = __floats2half2_rn(h0, h1);
            *(__half2*)(p + 32 + 4*t + 2) = __floats2half2_rn(h2, h3);
        }
    }
}

// ---------------------------------------------------------------------------
// 5) Flash v3: Q tile 256, 8 warps x 32 rows (2 m-blocks), fp16 m16n8k16.
//    K/V register-staged prefetch (LDG for kt+1 issued during kt compute).
//    Smem (halves): Qs[256][72] Ks[64][72] Vt[64][72] Ps[256][72] = 92160 B
//    1 CTA/SM.
// ---------------------------------------------------------------------------
#define FQ3 0
#define FK3 (256*72)
#define FV3 (FK3 + 64*72)
#define FP3 (FV3 + 64*72)
#define F3_SMEM_BYTES ((FP3 + 256*72)*2)

__global__ void __launch_bounds__(256) flash_h(
    const h16* __restrict__ q, const h16* __restrict__ k,
    const h16* __restrict__ v, h16* __restrict__ o)
{
    extern __shared__ h16 smh[];
    h16* Qs = smh + FQ3;
    h16* Ks = smh + FK3;
    h16* Vt = smh + FV3;
    h16* Ps = smh + FP3;

    const int qt = blockIdx.x, bh = blockIdx.y;
    const int b = bh >> 4, h = bh & 15;
    const int tid = threadIdx.x;
    const int lane = tid & 31, warp = tid >> 5;
    const int grp = lane >> 2, tig = lane & 3;
    const int wrow = warp * 32;
    const h16* qb = q + (size_t)b*NT*DIM + h*HD;
    const h16* kb = k + (size_t)b*NT*DIM + h*HD;
    const h16* vb = v + (size_t)b*NT*DIM + h*HD;

    // Q tile: 256 rows, scaled by exact 0.125
    const __half2 mk = __floats2half2_rn(0.125f, 0.125f);
    #pragma unroll
    for (int i = 0; i < 8; i++) {
        int idx = tid + i*256;
        int r = idx >> 3, c8 = (idx & 7) * 8;
        uint4 u = *(const uint4*)(qb + (size_t)(qt*256 + r)*DIM + c8);
        __half2* hp = (__half2*)&u;
        hp[0] = __hmul2(hp[0], mk); hp[1] = __hmul2(hp[1], mk);
        hp[2] = __hmul2(hp[2], mk); hp[3] = __hmul2(hp[3], mk);
        *(uint4*)&Qs[r*72 + c8] = u;
    }

    // register-staged K/V (16 halves each per thread)
    uint4 kr[2], vr[2];
    auto ldkv = [&](int kt){
        #pragma unroll
        for (int i = 0; i < 2; i++) {
            int idx = tid + i*256;
            int r = idx >> 3, c8 = (idx & 7) * 8;
            kr[i] = *(const uint4*)(kb + (size_t)(kt*64 + r)*DIM + c8);
            vr[i] = *(const uint4*)(vb + (size_t)(kt*64 + r)*DIM + c8);
        }
    };
    auto stkv = [&](){
        #pragma unroll
        for (int i = 0; i < 2; i++) {
            int idx = tid + i*256;
            int r = idx >> 3, c8 = (idx & 7) * 8;
            *(uint4*)&Ks[r*72 + c8] = kr[i];
            const h16* t = (const h16*)&vr[i];
            #pragma unroll
            for (int u8 = 0; u8 < 8; u8++)
                Vt[(c8+u8)*72 + r] = t[u8];
        }
    };

    float O[2][8][4];
    #pragma unroll
    for (int m2 = 0; m2 < 2; m2++)
        #pragma unroll
        for (int i = 0; i < 8; i++)
            #pragma unroll
            for (int j = 0; j < 4; j++) O[m2][i][j] = 0.f;
    float mM[2][2], lL[2][2];
    #pragma unroll
    for (int m2 = 0; m2 < 2; m2++) {
        mM[m2][0] = -1e30f; mM[m2][1] = -1e30f;
        lL[m2][0] = 0.f;    lL[m2][1] = 0.f;
    }

    ldkv(0);
    for (int kt = 0; kt < NT/64; kt++) {
        __syncthreads();          // previous iteration's smem reads done
        stkv();
        __syncthreads();
        if (kt + 1 < NT/64) ldkv(kt + 1);   // in flight during compute

        // S = Q @ K^T : 2 m-blocks x 8 n-blocks per warp
        float s[2][8][4];
        #pragma unroll
        for (int m2 = 0; m2 < 2; m2++)
            #pragma unroll
            for (int i = 0; i < 8; i++)
                #pragma unroll
                for (int j = 0; j < 4; j++) s[m2][i][j] = 0.f;
        #pragma unroll
        for (int kk = 0; kk < 64; kk += 16) {
            uint32_t bb[8][2];
            #pragma unroll
            for (int nb = 0; nb < 8; nb++) {
                int c = nb*8 + grp;
                bb[nb][0] = *(const uint32_t*)&Ks[c*72 + kk + 2*tig];
                bb[nb][1] = *(const uint32_t*)&Ks[c*72 + kk + 2*tig + 8];
            }
            #pragma unroll
            for (int m2 = 0; m2 < 2; m2++) {
                int r = wrow + m2*16 + grp;
                uint32_t a[4];
                a[0] = *(const uint32_t*)&Qs[r    *72 + kk + 2*tig];
                a[1] = *(const uint32_t*)&Qs[(r+8)*72 + kk + 2*tig];
                a[2] = *(const uint32_t*)&Qs[r    *72 + kk + 2*tig + 8];
                a[3] = *(const uint32_t*)&Qs[(r+8)*72 + kk + 2*tig + 8];
                #pragma unroll
                for (int nb = 0; nb < 8; nb++)
                    mma_h(s[m2][nb], a, bb[nb]);
            }
        }

        // online softmax per m-block (rows grp, grp+8)
        #pragma unroll
        for (int m2 = 0; m2 < 2; m2++) {
            float mx0 = -1e30f, mx1 = -1e30f;
            #pragma unroll
            for (int nb = 0; nb < 8; nb++) {
                mx0 = fmaxf(mx0, fmaxf(s[m2][nb][0], s[m2][nb][1]));
                mx1 = fmaxf(mx1, fmaxf(s[m2][nb][2], s[m2][nb][3]));
            }
            mx0 = fmaxf(mx0, __shfl_xor_sync(0xffffffffu, mx0, 1));
            mx0 = fmaxf(mx0, __shfl_xor_sync(0xffffffffu, mx0, 2));
            mx1 = fmaxf(mx1, __shfl_xor_sync(0xffffffffu, mx1, 1));
            mx1 = fmaxf(mx1, __shfl_xor_sync(0xffffffffu, mx1, 2));
            float nm0 = fmaxf(mM[m2][0], mx0), nm1 = fmaxf(mM[m2][1], mx1);
            float a0 = __expf(mM[m2][0] - nm0), a1 = __expf(mM[m2][1] - nm1);
            float rs0 = 0.f, rs1 = 0.f;
            int r = wrow + m2*16 + grp;
            #pragma unroll
            for (int nb = 0; nb < 8; nb++) {
                __half2 hp0 = __floats2half2_rn(__expf(s[m2][nb][0] - nm0),
                                                __expf(s[m2][nb][1] - nm0));
                __half2 hp1 = __floats2half2_rn(__expf(s[m2][nb][2] - nm1),
                                                __expf(s[m2][nb][3] - nm1));
                float2 f0 = __half22float2(hp0), f1 = __half22float2(hp1);
                rs0 += f0.x + f0.y; rs1 += f1.x + f1.y;
                *(__half2*)&Ps[r    *72 + nb*8 + 2*tig] = hp0;
                *(__half2*)&Ps[(r+8)*72 + nb*8 + 2*tig] = hp1;
                O[m2][nb][0] *= a0; O[m2][nb][1] *= a0;
                O[m2][nb][2] *= a1; O[m2][nb][3] *= a1;
            }
            rs0 += __shfl_xor_sync(0xffffffffu, rs0, 1);
            rs0 += __shfl_xor_sync(0xffffffffu, rs0, 2);
            rs1 += __shfl_xor_sync(0xffffffffu, rs1, 1);
            rs1 += __shfl_xor_sync(0xffffffffu, rs1, 2);
            lL[m2][0] = lL[m2][0]*a0 + rs0;
            lL[m2][1] = lL[m2][1]*a1 + rs1;
            mM[m2][0] = nm0; mM[m2][1] = nm1;
        }
        __syncwarp();       // P rows are warp-private

        // O += P @ V
        #pragma unroll
        for (int kk = 0; kk < 64; kk += 16) {
            uint32_t bb[8][2];
            #pragma unroll
            for (int nb = 0; nb < 8; nb++) {
                int d = nb*8 + grp;
                bb[nb][0] = *(const uint32_t*)&Vt[d*72 + kk + 2*tig];
                bb[nb][1] = *(const uint32_t*)&Vt[d*72 + kk + 2*tig + 8];
            }
            #pragma unroll
            for (int m2 = 0; m2 < 2; m2++) {
                int r = wrow + m2*16 + grp;
                uint32_t a[4];
                a[0] = *(const uint32_t*)&Ps[r    *72 + kk + 2*tig];
                a[1] = *(const uint32_t*)&Ps[(r+8)*72 + kk + 2*tig];
                a[2] = *(const uint32_t*)&Ps[r    *72 + kk + 2*tig + 8];
                a[3] = *(const uint32_t*)&Ps[(r+8)*72 + kk + 2*tig + 8];
                #pragma unroll
                for (int nb = 0; nb < 8; nb++)
                    mma_h(O[m2][nb], a, bb[nb]);
            }
        }
        __syncwarp();
    }

    #pragma unroll
    for (int m2 = 0; m2 < 2; m2++) {
        float i0 = 1.f/lL[m2][0], i1 = 1.f/lL[m2][1];
        int row = qt*256 + wrow + m2*16 + grp;
        #pragma unroll
        for (int nb = 0; nb < 8; nb++) {
            size_t off = (size_t)(b*NT + row)*DIM + h*HD + nb*8 + 2*tig;
            *(__half2*)(o + off)         = __floats2half2_rn(O[m2][nb][0]*i0,
                                                             O[m2][nb][1]*i0);
            *(__half2*)(o + off + 8*DIM) = __floats2half2_rn(O[m2][nb][2]*i1,
                                                             O[m2][nb][3]*i1);
        }
    }
}

// ---------------------------------------------------------------------------
// Host launcher
// ---------------------------------------------------------------------------
extern "C" void kernel_launch(void* const* d_in, const int* in_sizes, int n_in,
                              void* d_out, int out_size)
{
    const float* x       = (const float*)d_in[0];
    const float* t_emb   = (const float*)d_in[1];
    const float* norm1_g = (const float*)d_in[2];
    const float* norm1_b = (const float*)d_in[3];
    const float* Wq      = (const float*)d_in[4];
    const float* Wk      = (const float*)d_in[5];
    const float* Wv      = (const float*)d_in[6];
    const float* Wo      = (const float*)d_in[7];
    const float* norm2_g = (const float*)d_in[8];
    const float* norm2_b = (const float*)d_in[9];
    const float* W1      = (const float*)d_in[10];
    const float* W2      = (const float*)d_in[11];
    const float* ada_W   = (const float*)d_in[12];
    const float* ada_b   = (const float*)d_in[13];
    float* out = (float*)d_out;

    float *mod;
    h16 *xn, *q, *k, *v, *attn, *hbuf, *wt;
    cudaGetSymbolAddress((void**)&mod,  g_mod);
    cudaGetSymbolAddress((void**)&xn,   g_xn);
    cudaGetSymbolAddress((void**)&q,    g_q);
    cudaGetSymbolAddress((void**)&k,    g_k);
    cudaGetSymbolAddress((void**)&v,    g_v);
    cudaGetSymbolAddress((void**)&attn, g_attn);
    cudaGetSymbolAddress((void**)&hbuf, g_h);
    cudaGetSymbolAddress((void**)&wt,   g_wt);

    cudaFuncSetAttribute(gemm_h<0>, cudaFuncAttributeMaxDynamicSharedMemorySize, G_SMEM_BYTES);
    cudaFuncSetAttribute(gemm_h<1>, cudaFuncAttributeMaxDynamicSharedMemorySize, G_SMEM_BYTES);
    cudaFuncSetAttribute(gemm_h<2>, cudaFuncAttributeMaxDynamicSharedMemorySize, G_SMEM_BYTES);
    cudaFuncSetAttribute(flash_h,   cudaFuncAttributeMaxDynamicSharedMemorySize, F3_SMEM_BYTES);

    // launch 0: fused weight transpose -> fp16 [N][K]
    trans_all<<<12288, 256>>>(Wq, Wk, Wv, Wo, W1, W2, wt);
    // launch 1: adaLN modulation
    silu_mod_kernel<<<dim3(24, BT), 256>>>(t_emb, ada_W, ada_b, mod);
    // launch 2: LN1 + modulate -> fp16
    ln_mod_kernel<<<ROWS, 256>>>(x, xn, norm1_g, norm1_b, mod, 0, 1);
    // launch 3: fused QKV
    gemm_h<0><<<dim3(24, ROWS/128), 256, G_SMEM_BYTES>>>(
        xn, wt, DIM, DIM, q, k, v, nullptr, nullptr, nullptr);
    // launch 4: RoPE
    rope_kernel<<<(BT*NT*HEADS)/256, 256>>>(q, k);
    // launch 5: attention (flash v3: Q tile 256)
    flash_h<<<dim3(NT/256, BT*HEADS), 256, F3_SMEM_BYTES>>>(q, k, v, attn);
    // launch 6: out proj + gated residual (gate_msa = chunk 2) -> d_out
    gemm_h<2><<<dim3(8, ROWS/128), 256, G_SMEM_BYTES>>>(
        attn, wt + W_O, DIM, DIM, nullptr, nullptr, nullptr,
        out, mod + 2*DIM, x);
    // launch 7: LN2 + modulate -> fp16
    ln_mod_kernel<<<ROWS, 256>>>(out, xn, norm2_g, norm2_b, mod, 3, 4);
    // launch 8: MLP up + exact GELU -> fp16
    gemm_h<1><<<dim3(32, ROWS/128), 256, G_SMEM_BYTES>>>(
        xn, wt + W_1, DIM, MLPD, hbuf, nullptr, nullptr,
        nullptr, nullptr, nullptr);
    // launch 9: MLP down + gated residual (gate_mlp = chunk 5) -> d_out
    gemm_h<2><<<dim3(8, ROWS/128), 256, G_SMEM_BYTES>>>(
        hbuf, wt + W_2, MLPD, DIM, nullptr, nullptr, nullptr,
        out, mod + 5*DIM, out);
}

// round 16
// speedup vs baseline: 1.6450x; 1.0307x over previous
#include <cuda_runtime.h>
#include <cuda_fp16.h>
#include <math.h>
#include <stdint.h>

#define DIM   1024
#define BT    2
#define NT    2048
#define HEADS 16
#define HD    64
#define MLPD  4096
#define ROWS  (BT*NT)

typedef __half h16;

// ---------------------------------------------------------------------------
// Scratch (static device globals)
// ---------------------------------------------------------------------------
__device__ float g_mod [BT*6*DIM];
__device__ __align__(16) h16 g_xn  [ROWS*DIM];
__device__ __align__(16) h16 g_q   [ROWS*DIM];
__device__ __align__(16) h16 g_k   [ROWS*DIM];
__device__ __align__(16) h16 g_v   [ROWS*DIM];
__device__ __align__(16) h16 g_attn[ROWS*DIM];
__device__ __align__(16) h16 g_h   [(size_t)ROWS*MLPD];
// fp16 weights, transposed to [N][K]: QKV (3M), Wo (1M), W1 (4M), W2 (4M)
__device__ __align__(16) h16 g_wt  [12*1024*1024];

#define W_O (3*1024*1024)
#define W_1 (4*1024*1024)
#define W_2 (8*1024*1024)

// ---------------------------------------------------------------------------
// PTX helpers
// ---------------------------------------------------------------------------
__device__ __forceinline__ uint32_t smaddr(const void* p){
    return (uint32_t)__cvta_generic_to_shared(p);
}
__device__ __forceinline__ void cp16(uint32_t d, const void* s){
    asm volatile("cp.async.cg.shared.global [%0], [%1], 16;\n" :: "r"(d), "l"(s));
}
__device__ __forceinline__ void cp_commit(){
    asm volatile("cp.async.commit_group;\n" ::);
}
__device__ __forceinline__ void cp_wait1(){
    asm volatile("cp.async.wait_group 1;\n" ::);
}
// D(16x8,f32) += A(16x16 f16, row) * B(16x8 f16, col)
__device__ __forceinline__ void mma_h(float* c, const uint32_t* a, const uint32_t* b){
    asm volatile(
        "mma.sync.aligned.m16n8k16.row.col.f32.f16.f16.f32 "
        "{%0,%1,%2,%3}, {%4,%5,%6,%7}, {%8,%9}, {%0,%1,%2,%3};\n"
        : "+f"(c[0]), "+f"(c[1]), "+f"(c[2]), "+f"(c[3])
        : "r"(a[0]), "r"(a[1]), "r"(a[2]), "r"(a[3]),
          "r"(b[0]), "r"(b[1]));
}

// ---------------------------------------------------------------------------
// 0) ONE fused weight prepass: fp32 W[K][N] -> fp16 Wt[N][K] for all 6 mats
// ---------------------------------------------------------------------------
__global__ void __launch_bounds__(256) trans_all(
    const float* __restrict__ Wq, const float* __restrict__ Wk,
    const float* __restrict__ Wv, const float* __restrict__ Wo,
    const float* __restrict__ W1, const float* __restrict__ W2,
    h16* __restrict__ wt)
{
    __shared__ float t[32][33];
    int bid = blockIdx.x;
    const float* src; h16* dst; int K, N, kb, nb;
    if (bid < 4096) {
        int m = bid >> 10, tile = bid & 1023;
        src = (m==0)?Wq:(m==1)?Wk:(m==2)?Wv:Wo;
        dst = wt + (size_t)m*1024*1024;
        K = 1024; N = 1024;
        kb = (tile >> 5)*32; nb = (tile & 31)*32;
    } else if (bid < 8192) {
        int tile = bid - 4096;
        src = W1; dst = wt + W_1; K = 1024; N = 4096;
        kb = (tile >> 7)*32; nb = (tile & 127)*32;
    } else {
        int tile = bid - 8192;
        src = W2; dst = wt + W_2; K = 4096; N = 1024;
        kb = (tile >> 5)*32; nb = (tile & 31)*32;
    }
    int tx = threadIdx.x & 31, ty = threadIdx.x >> 5;
    #pragma unroll
    for (int j = 0; j < 32; j += 8)
        t[ty+j][tx] = src[(size_t)(kb+ty+j)*N + nb + tx];
    __syncthreads();
    #pragma unroll
    for (int j = 0; j < 32; j += 8)
        dst[(size_t)(nb+ty+j)*K + kb + tx] = __float2half(t[tx][ty+j]);
}

// ---------------------------------------------------------------------------
// 1) mod = silu(t_emb) @ ada_W + ada_b
// ---------------------------------------------------------------------------
__global__ void __launch_bounds__(256) silu_mod_kernel(
    const float* __restrict__ t_emb, const float* __restrict__ adaW,
    const float* __restrict__ adab, float* __restrict__ mod)
{
    __shared__ float st[DIM];
    int b = blockIdx.y;
    int j = blockIdx.x * 256 + threadIdx.x;
    for (int i = threadIdx.x; i < DIM; i += 256) {
        float t = t_emb[b*DIM + i];
        st[i] = t / (1.f + __expf(-t));
    }
    __syncthreads();
    float acc = 0.f;
    #pragma unroll 4
    for (int kk = 0; kk < DIM; kk++)
        acc += st[kk] * adaW[(size_t)kk*6*DIM + j];
    mod[b*6*DIM + j] = acc + adab[j];
}

// ---------------------------------------------------------------------------
// 2) LN + adaLN modulation -> fp16
// ---------------------------------------------------------------------------
__global__ void __launch_bounds__(256) ln_mod_kernel(
    const float* __restrict__ x, h16* __restrict__ out,
    const float* __restrict__ g, const float* __restrict__ bb,
    const float* __restrict__ mod, int shift_chunk, int scale_chunk)
{
    int row = blockIdx.x;
    int b   = row >> 11;
    int tid = threadIdx.x;
    const float* xr = x + (size_t)row*DIM;
    float4 xv = *(const float4*)(xr + tid*4);
    float s  = xv.x + xv.y + xv.z + xv.w;
    float s2 = xv.x*xv.x + xv.y*xv.y + xv.z*xv.z + xv.w*xv.w;
    #pragma unroll
    for (int o = 16; o > 0; o >>= 1) {
        s  += __shfl_xor_sync(0xffffffffu, s,  o);
        s2 += __shfl_xor_sync(0xffffffffu, s2, o);
    }
    __shared__ float ws[8], ws2[8];
    __shared__ float smu, srstd;
    int wid = tid >> 5;
    if ((tid & 31) == 0) { ws[wid] = s; ws2[wid] = s2; }
    __syncthreads();
    if (tid == 0) {
        float S = 0.f, S2 = 0.f;
        #pragma unroll
        for (int i = 0; i < 8; i++) { S += ws[i]; S2 += ws2[i]; }
        float mu  = S  * (1.f/DIM);
        float var = S2 * (1.f/DIM) - mu*mu;
        smu = mu; srstd = rsqrtf(var + 1e-5f);
    }
    __syncthreads();
    float mu = smu, rstd = srstd;
    int c = tid*4;
    const float* mb = mod + b*6*DIM;
    float4 gv = *(const float4*)(g  + c);
    float4 bv = *(const float4*)(bb + c);
    float4 sc = *(const float4*)(mb + scale_chunk*DIM + c);
    float4 sh = *(const float4*)(mb + shift_chunk*DIM + c);
    float y0 = ((xv.x-mu)*rstd*gv.x + bv.x)*(1.f+sc.x) + sh.x;
    float y1 = ((xv.y-mu)*rstd*gv.y + bv.y)*(1.f+sc.y) + sh.y;
    float y2 = ((xv.z-mu)*rstd*gv.z + bv.z)*(1.f+sc.z) + sh.z;
    float y3 = ((xv.w-mu)*rstd*gv.w + bv.w)*(1.f+sc.w) + sh.w;
    h16* o = out + (size_t)row*DIM + c;
    *(__half2*)o       = __floats2half2_rn(y0, y1);
    *(__half2*)(o + 2) = __floats2half2_rn(y2, y3);
}

// ---------------------------------------------------------------------------
// fp16 GEMM v2: BM=BN=128, BK=64; 128 threads = 4 warps (2M x 2N);
//   warp tile 64x64 (4 m-blocks x 8 n-blocks) -> bytes/MAC = 0.0625,
//   smem cycles == tensor cycles (was 1.5:1 at warp 32x64).
//   2 CTAs/SM (72 KB smem each, regs capped by launch_bounds(128,2)).
//   EPI: 0 = fp16 store into one of 3 outputs (QKV, grid.x=24)
//        1 = exact GELU -> fp16
//        2 = res + gate*acc -> fp32 (d_out)
// ---------------------------------------------------------------------------
#define GTILE (128*72)
#define GBUF  (2*GTILE)
#define GBUF_BYTES (GBUF*2)
#define G_SMEM_BYTES (2*GBUF_BYTES)

template<int EPI>
__global__ void __launch_bounds__(128, 2) gemm_h(
    const h16* __restrict__ A, const h16* __restrict__ Wt,
    int K, int Nc,
    h16* __restrict__ o16a, h16* __restrict__ o16b, h16* __restrict__ o16c,
    float* __restrict__ ofp,
    const float* __restrict__ gate, const float* __restrict__ res)
{
    extern __shared__ h16 smh[];
    const int tid  = threadIdx.x;
    const int lane = tid & 31, warp = tid >> 5;
    const int grp  = lane >> 2, tig = lane & 3;
    const int wm   = warp & 1,  wn  = warp >> 1;   // 2 x 2 warps
    const int m0   = blockIdx.y * 128;
    const int n0g  = blockIdx.x * 128;
    const uint32_t smb = smaddr(smh);
    const int nk = K >> 6;

    float acc[4][8][4];
    #pragma unroll
    for (int i = 0; i < 4; i++)
        #pragma unroll
        for (int j = 0; j < 8; j++)
            #pragma unroll
            for (int t = 0; t < 4; t++) acc[i][j][t] = 0.f;

    auto prefetch = [&](int kc, int bufi){
        uint32_t base = smb + bufi*GBUF_BYTES;
        #pragma unroll
        for (int i = 0; i < 8; i++) {
            int idx = tid + i*128;
            int r = idx >> 3, c8 = (idx & 7) * 8;
            cp16(base + (uint32_t)(r*72 + c8)*2u,
                 A + (size_t)(m0 + r)*K + kc*64 + c8);
        }
        #pragma unroll
        for (int i = 0; i < 8; i++) {
            int idx = tid + i*128;
            int r = idx >> 3, c8 = (idx & 7) * 8;
            cp16(base + (uint32_t)(GTILE + r*72 + c8)*2u,
                 Wt + (size_t)(n0g + r)*K + kc*64 + c8);
        }
        cp_commit();
    };

    prefetch(0, 0);
    if (nk > 1) prefetch(1, 1); else cp_commit();

    int buf = 0;
    for (int kc = 0; kc < nk; kc++) {
        cp_wait1();
        __syncthreads();
        const h16* As = smh + buf*GBUF;
        const h16* Bs = As + GTILE;
        #pragma unroll
        for (int kk = 0; kk < 64; kk += 16) {
            uint32_t a[4][4], b[8][2];
            #pragma unroll
            for (int ma = 0; ma < 4; ma++) {
                int r = wm*64 + ma*16 + grp;
                a[ma][0] = *(const uint32_t*)&As[r    *72 + kk + 2*tig];
                a[ma][1] = *(const uint32_t*)&As[(r+8)*72 + kk + 2*tig];
                a[ma][2] = *(const uint32_t*)&As[r    *72 + kk + 2*tig + 8];
                a[ma][3] = *(const uint32_t*)&As[(r+8)*72 + kk + 2*tig + 8];
            }
            #pragma unroll
            for (int nb = 0; nb < 8; nb++) {
                int c = wn*64 + nb*8 + grp;
                b[nb][0] = *(const uint32_t*)&Bs[c*72 + kk + 2*tig];
                b[nb][1] = *(const uint32_t*)&Bs[c*72 + kk + 2*tig + 8];
            }
            #pragma unroll
            for (int ma = 0; ma < 4; ma++)
                #pragma unroll
                for (int nb = 0; nb < 8; nb++)
                    mma_h(acc[ma][nb], a[ma], b[nb]);
        }
        __syncthreads();
        if (kc + 2 < nk) prefetch(kc + 2, buf);
        else cp_commit();
        buf ^= 1;
    }

    #pragma unroll
    for (int ma = 0; ma < 4; ma++) {
        int r0 = m0 + wm*64 + ma*16 + grp;
        #pragma unroll
        for (int nb = 0; nb < 8; nb++) {
            int cl = wn*64 + nb*8 + 2*tig;
            float o0 = acc[ma][nb][0], o1 = acc[ma][nb][1];
            float o2 = acc[ma][nb][2], o3 = acc[ma][nb][3];
            if (EPI == 0) {
                int mat = blockIdx.x >> 3;
                h16* O = (mat == 0) ? o16a : (mat == 1) ? o16b : o16c;
                int c = ((blockIdx.x & 7) * 128) + cl;
                *(__half2*)(O + (size_t)r0    *DIM + c) = __floats2half2_rn(o0, o1);
                *(__half2*)(O + (size_t)(r0+8)*DIM + c) = __floats2half2_rn(o2, o3);
            } else if (EPI == 1) {
                int c = n0g + cl;
                o0 = 0.5f*o0*(1.f + erff(o0*0.70710678f));
                o1 = 0.5f*o1*(1.f + erff(o1*0.70710678f));
                o2 = 0.5f*o2*(1.f + erff(o2*0.70710678f));
                o3 = 0.5f*o3*(1.f + erff(o3*0.70710678f));
                *(__half2*)(o16a + (size_t)r0    *Nc + c) = __floats2half2_rn(o0, o1);
                *(__half2*)(o16a + (size_t)(r0+8)*Nc + c) = __floats2half2_rn(o2, o3);
            } else {
                int c = n0g + cl;
                int bi = r0 >> 11;
                float2 g2 = *(const float2*)(gate + bi*6*DIM + c);
                float2 ra = *(const float2*)(res + (size_t)r0    *Nc + c);
                float2 rb = *(const float2*)(res + (size_t)(r0+8)*Nc + c);
                o0 = ra.x + g2.x*o0; o1 = ra.y + g2.y*o1;
                o2 = rb.x + g2.x*o2; o3 = rb.y + g2.y*o3;
                *(float2*)(ofp + (size_t)r0    *Nc + c) = make_float2(o0, o1);
                *(float2*)(ofp + (size_t)(r0+8)*Nc + c) = make_float2(o2, o3);
            }
        }
    }
}

// ---------------------------------------------------------------------------
// 4) RoPE on fp16 q,k (fp32 math inside)
// ---------------------------------------------------------------------------
__global__ void __launch_bounds__(256) rope_kernel(h16* __restrict__ q,
                                                   h16* __restrict__ k)
{
    int idx = blockIdx.x*256 + threadIdx.x;
    int n = (idx >> 4) & (NT-1);
    float cs[32], sn[32];
    #pragma unroll
    for (int j = 0; j < 32; j++) {
        float invf = expf((float)j * -0.2878231366f);
        float ang  = (float)n * invf;
        sincosf(ang, &sn[j], &cs[j]);
    }
    h16* ptrs[2]; ptrs[0] = q + (size_t)idx*64; ptrs[1] = k + (size_t)idx*64;
    #pragma unroll
    for (int tpi = 0; tpi < 2; tpi++) {
        h16* p = ptrs[tpi];
        float buf[64];
        #pragma unroll
        for (int u = 0; u < 16; u++) {
            __half2 t = *(const __half2*)(p + u*4);
            __half2 t2 = *(const __half2*)(p + u*4 + 2);
            float2 f = __half22float2(t), f2 = __half22float2(t2);
            buf[u*4+0] = f.x;  buf[u*4+1] = f.y;
            buf[u*4+2] = f2.x; buf[u*4+3] = f2.y;
        }
        #pragma unroll
        for (int t = 0; t < 8; t++) {
            float l0 = buf[4*t+0]*cs[4*t+0] - buf[8*t+1]*sn[4*t+0];
            float l1 = buf[4*t+1]*cs[4*t+1] - buf[8*t+3]*sn[4*t+1];
            float l2 = buf[4*t+2]*cs[4*t+2] - buf[8*t+5]*sn[4*t+2];
            float l3 = buf[4*t+3]*cs[4*t+3] - buf[8*t+7]*sn[4*t+3];
            float h0 = buf[32+4*t+0]*cs[4*t+0] + buf[8*t+0]*sn[4*t+0];
            float h1 = buf[32+4*t+1]*cs[4*t+1] + buf[8*t+2]*sn[4*t+1];
            float h2 = buf[32+4*t+2]*cs[4*t+2] + buf[8*t+4]*sn[4*t+2];
            float h3 = buf[32+4*t+3]*cs[4*t+3] + buf[8*t+6]*sn[4*t+3];
            *(__half2*)(p + 4*t)          = __floats2half2_rn(l0, l1);
            *(__half2*)(p + 4*t + 2)      = __floats2half2_rn(l2, l3);
            *(__half2*)(p + 32 + 4*t)     = __floats2half2_rn(h0, h1);
            *(__half2*)(p + 32 + 4*t + 2) = __floats2half2_rn(h2, h3);
        }
    }
}

// ---------------------------------------------------------------------------
// 5) Flash v3 (unchanged from R14-pass): Q tile 256, 8 warps x 32 rows.
// ---------------------------------------------------------------------------
#define FQ3 0
#define FK3 (256*72)
#define FV3 (FK3 + 64*72)
#define FP3 (FV3 + 64*72)
#define F3_SMEM_BYTES ((FP3 + 256*72)*2)

__global__ void __launch_bounds__(256) flash_h(
    const h16* __restrict__ q, const h16* __restrict__ k,
    const h16* __restrict__ v, h16* __restrict__ o)
{
    extern __shared__ h16 smh[];
    h16* Qs = smh + FQ3;
    h16* Ks = smh + FK3;
    h16* Vt = smh + FV3;
    h16* Ps = smh + FP3;

    const int qt = blockIdx.x, bh = blockIdx.y;
    const int b = bh >> 4, h = bh & 15;
    const int tid = threadIdx.x;
    const int lane = tid & 31, warp = tid >> 5;
    const int grp = lane >> 2, tig = lane & 3;
    const int wrow = warp * 32;
    const h16* qb = q + (size_t)b*NT*DIM + h*HD;
    const h16* kb = k + (size_t)b*NT*DIM + h*HD;
    const h16* vb = v + (size_t)b*NT*DIM + h*HD;

    const __half2 mk = __floats2half2_rn(0.125f, 0.125f);
    #pragma unroll
    for (int i = 0; i < 8; i++) {
        int idx = tid + i*256;
        int r = idx >> 3, c8 = (idx & 7) * 8;
        uint4 u = *(const uint4*)(qb + (size_t)(qt*256 + r)*DIM + c8);
        __half2* hp = (__half2*)&u;
        hp[0] = __hmul2(hp[0], mk); hp[1] = __hmul2(hp[1], mk);
        hp[2] = __hmul2(hp[2], mk); hp[3] = __hmul2(hp[3], mk);
        *(uint4*)&Qs[r*72 + c8] = u;
    }

    uint4 kr[2], vr[2];
    auto ldkv = [&](int kt){
        #pragma unroll
        for (int i = 0; i < 2; i++) {
            int idx = tid + i*256;
            int r = idx >> 3, c8 = (idx & 7) * 8;
            kr[i] = *(const uint4*)(kb + (size_t)(kt*64 + r)*DIM + c8);
            vr[i] = *(const uint4*)(vb + (size_t)(kt*64 + r)*DIM + c8);
        }
    };
    auto stkv = [&](){
        #pragma unroll
        for (int i = 0; i < 2; i++) {
            int idx = tid + i*256;
            int r = idx >> 3, c8 = (idx & 7) * 8;
            *(uint4*)&Ks[r*72 + c8] = kr[i];
            const h16* t = (const h16*)&vr[i];
            #pragma unroll
            for (int u8 = 0; u8 < 8; u8++)
                Vt[(c8+u8)*72 + r] = t[u8];
        }
    };

    float O[2][8][4];
    #pragma unroll
    for (int m2 = 0; m2 < 2; m2++)
        #pragma unroll
        for (int i = 0; i < 8; i++)
            #pragma unroll
            for (int j = 0; j < 4; j++) O[m2][i][j] = 0.f;
    float mM[2][2], lL[2][2];
    #pragma unroll
    for (int m2 = 0; m2 < 2; m2++) {
        mM[m2][0] = -1e30f; mM[m2][1] = -1e30f;
        lL[m2][0] = 0.f;    lL[m2][1] = 0.f;
    }

    ldkv(0);
    for (int kt = 0; kt < NT/64; kt++) {
        __syncthreads();
        stkv();
        __syncthreads();
        if (kt + 1 < NT/64) ldkv(kt + 1);

        float s[2][8][4];
        #pragma unroll
        for (int m2 = 0; m2 < 2; m2++)
            #pragma unroll
            for (int i = 0; i < 8; i++)
                #pragma unroll
                for (int j = 0; j < 4; j++) s[m2][i][j] = 0.f;
        #pragma unroll
        for (int kk = 0; kk < 64; kk += 16) {
            uint32_t bb[8][2];
            #pragma unroll
            for (int nb = 0; nb < 8; nb++) {
                int c = nb*8 + grp;
                bb[nb][0] = *(const uint32_t*)&Ks[c*72 + kk + 2*tig];
                bb[nb][1] = *(const uint32_t*)&Ks[c*72 + kk + 2*tig + 8];
            }
            #pragma unroll
            for (int m2 = 0; m2 < 2; m2++) {
                int r = wrow + m2*16 + grp;
                uint32_t a[4];
                a[0] = *(const uint32_t*)&Qs[r    *72 + kk + 2*tig];
                a[1] = *(const uint32_t*)&Qs[(r+8)*72 + kk + 2*tig];
                a[2] = *(const uint32_t*)&Qs[r    *72 + kk + 2*tig + 8];
                a[3] = *(const uint32_t*)&Qs[(r+8)*72 + kk + 2*tig + 8];
                #pragma unroll
                for (int nb = 0; nb < 8; nb++)
                    mma_h(s[m2][nb], a, bb[nb]);
            }
        }

        #pragma unroll
        for (int m2 = 0; m2 < 2; m2++) {
            float mx0 = -1e30f, mx1 = -1e30f;
            #pragma unroll
            for (int nb = 0; nb < 8; nb++) {
                mx0 = fmaxf(mx0, fmaxf(s[m2][nb][0], s[m2][nb][1]));
                mx1 = fmaxf(mx1, fmaxf(s[m2][nb][2], s[m2][nb][3]));
            }
            mx0 = fmaxf(mx0, __shfl_xor_sync(0xffffffffu, mx0, 1));
            mx0 = fmaxf(mx0, __shfl_xor_sync(0xffffffffu, mx0, 2));
            mx1 = fmaxf(mx1, __shfl_xor_sync(0xffffffffu, mx1, 1));
            mx1 = fmaxf(mx1, __shfl_xor_sync(0xffffffffu, mx1, 2));
            float nm0 = fmaxf(mM[m2][0], mx0), nm1 = fmaxf(mM[m2][1], mx1);
            float a0 = __expf(mM[m2][0] - nm0), a1 = __expf(mM[m2][1] - nm1);
            float rs0 = 0.f, rs1 = 0.f;
            int r = wrow + m2*16 + grp;
            #pragma unroll
            for (int nb = 0; nb < 8; nb++) {
                __half2 hp0 = __floats2half2_rn(__expf(s[m2][nb][0] - nm0),
                                                __expf(s[m2][nb][1] - nm0));
                __half2 hp1 = __floats2half2_rn(__expf(s[m2][nb][2] - nm1),
                                                __expf(s[m2][nb][3] - nm1));
                float2 f0 = __half22float2(hp0), f1 = __half22float2(hp1);
                rs0 += f0.x + f0.y; rs1 += f1.x + f1.y;
                *(__half2*)&Ps[r    *72 + nb*8 + 2*tig] = hp0;
                *(__half2*)&Ps[(r+8)*72 + nb*8 + 2*tig] = hp1;
                O[m2][nb][0] *= a0; O[m2][nb][1] *= a0;
                O[m2][nb][2] *= a1; O[m2][nb][3] *= a1;
            }
            rs0 += __shfl_xor_sync(0xffffffffu, rs0, 1);
            rs0 += __shfl_xor_sync(0xffffffffu, rs0, 2);
            rs1 += __shfl_xor_sync(0xffffffffu, rs1, 1);
            rs1 += __shfl_xor_sync(0xffffffffu, rs1, 2);
            lL[m2][0] = lL[m2][0]*a0 + rs0;
            lL[m2][1] = lL[m2][1]*a1 + rs1;
            mM[m2][0] = nm0; mM[m2][1] = nm1;
        }
        __syncwarp();

        #pragma unroll
        for (int kk = 0; kk < 64; kk += 16) {
            uint32_t bb[8][2];
            #pragma unroll
            for (int nb = 0; nb < 8; nb++) {
                int d = nb*8 + grp;
                bb[nb][0] = *(const uint32_t*)&Vt[d*72 + kk + 2*tig];
                bb[nb][1] = *(const uint32_t*)&Vt[d*72 + kk + 2*tig + 8];
            }
            #pragma unroll
            for (int m2 = 0; m2 < 2; m2++) {
                int r = wrow + m2*16 + grp;
                uint32_t a[4];
                a[0] = *(const uint32_t*)&Ps[r    *72 + kk + 2*tig];
                a[1] = *(const uint32_t*)&Ps[(r+8)*72 + kk + 2*tig];
                a[2] = *(const uint32_t*)&Ps[r    *72 + kk + 2*tig + 8];
                a[3] = *(const uint32_t*)&Ps[(r+8)*72 + kk + 2*tig + 8];
                #pragma unroll
                for (int nb = 0; nb < 8; nb++)
                    mma_h(O[m2][nb], a, bb[nb]);
            }
        }
        __syncwarp();
    }

    #pragma unroll
    for (int m2 = 0; m2 < 2; m2++) {
        float i0 = 1.f/lL[m2][0], i1 = 1.f/lL[m2][1];
        int row = qt*256 + wrow + m2*16 + grp;
        #pragma unroll
        for (int nb = 0; nb < 8; nb++) {
            size_t off = (size_t)(b*NT + row)*DIM + h*HD + nb*8 + 2*tig;
            *(__half2*)(o + off)         = __floats2half2_rn(O[m2][nb][0]*i0,
                                                             O[m2][nb][1]*i0);
            *(__half2*)(o + off + 8*DIM) = __floats2half2_rn(O[m2][nb][2]*i1,
                                                             O[m2][nb][3]*i1);
        }
    }
}

// ---------------------------------------------------------------------------
// Host launcher
// ---------------------------------------------------------------------------
extern "C" void kernel_launch(void* const* d_in, const int* in_sizes, int n_in,
                              void* d_out, int out_size)
{
    const float* x       = (const float*)d_in[0];
    const float* t_emb   = (const float*)d_in[1];
    const float* norm1_g = (const float*)d_in[2];
    const float* norm1_b = (const float*)d_in[3];
    const float* Wq      = (const float*)d_in[4];
    const float* Wk      = (const float*)d_in[5];
    const float* Wv      = (const float*)d_in[6];
    const float* Wo      = (const float*)d_in[7];
    const float* norm2_g = (const float*)d_in[8];
    const float* norm2_b = (const float*)d_in[9];
    const float* W1      = (const float*)d_in[10];
    const float* W2      = (const float*)d_in[11];
    const float* ada_W   = (const float*)d_in[12];
    const float* ada_b   = (const float*)d_in[13];
    float* out = (float*)d_out;

    float *mod;
    h16 *xn, *q, *k, *v, *attn, *hbuf, *wt;
    cudaGetSymbolAddress((void**)&mod,  g_mod);
    cudaGetSymbolAddress((void**)&xn,   g_xn);
    cudaGetSymbolAddress((void**)&q,    g_q);
    cudaGetSymbolAddress((void**)&k,    g_k);
    cudaGetSymbolAddress((void**)&v,    g_v);
    cudaGetSymbolAddress((void**)&attn, g_attn);
    cudaGetSymbolAddress((void**)&hbuf, g_h);
    cudaGetSymbolAddress((void**)&wt,   g_wt);

    cudaFuncSetAttribute(gemm_h<0>, cudaFuncAttributeMaxDynamicSharedMemorySize, G_SMEM_BYTES);
    cudaFuncSetAttribute(gemm_h<1>, cudaFuncAttributeMaxDynamicSharedMemorySize, G_SMEM_BYTES);
    cudaFuncSetAttribute(gemm_h<2>, cudaFuncAttributeMaxDynamicSharedMemorySize, G_SMEM_BYTES);
    cudaFuncSetAttribute(flash_h,   cudaFuncAttributeMaxDynamicSharedMemorySize, F3_SMEM_BYTES);

    // launch 0: fused weight transpose -> fp16 [N][K]
    trans_all<<<12288, 256>>>(Wq, Wk, Wv, Wo, W1, W2, wt);
    // launch 1: adaLN modulation
    silu_mod_kernel<<<dim3(24, BT), 256>>>(t_emb, ada_W, ada_b, mod);
    // launch 2: LN1 + modulate -> fp16
    ln_mod_kernel<<<ROWS, 256>>>(x, xn, norm1_g, norm1_b, mod, 0, 1);
    // launch 3: fused QKV (128-thread CTAs, warp 64x64)
    gemm_h<0><<<dim3(24, ROWS/128), 128, G_SMEM_BYTES>>>(
        xn, wt, DIM, DIM, q, k, v, nullptr, nullptr, nullptr);
    // launch 4: RoPE
    rope_kernel<<<(BT*NT*HEADS)/256, 256>>>(q, k);
    // launch 5: attention (flash v3: Q tile 256)
    flash_h<<<dim3(NT/256, BT*HEADS), 256, F3_SMEM_BYTES>>>(q, k, v, attn);
    // launch 6: out proj + gated residual (gate_msa = chunk 2) -> d_out
    gemm_h<2><<<dim3(8, ROWS/128), 128, G_SMEM_BYTES>>>(
        attn, wt + W_O, DIM, DIM, nullptr, nullptr, nullptr,
        out, mod + 2*DIM, x);
    // launch 7: LN2 + modulate -> fp16
    ln_mod_kernel<<<ROWS, 256>>>(out, xn, norm2_g, norm2_b, mod, 3, 4);
    // launch 8: MLP up + exact GELU -> fp16
    gemm_h<1><<<dim3(32, ROWS/128), 128, G_SMEM_BYTES>>>(
        xn, wt + W_1, DIM, MLPD, hbuf, nullptr, nullptr,
        nullptr, nullptr, nullptr);
    // launch 9: MLP down + gated residual (gate_mlp = chunk 5) -> d_out
    gemm_h<2><<<dim3(8, ROWS/128), 128, G_SMEM_BYTES>>>(
        hbuf, wt + W_2, MLPD, DIM, nullptr, nullptr, nullptr,
        out, mod + 5*DIM, out);
}